// round 5
// baseline (speedup 1.0000x reference)
#include <cuda_runtime.h>
#include <math.h>

// ---------------- scratch (device globals; no allocation) ----------------
__device__ float g_k1  [16 * 512 * 200];   // key conv1 out
__device__ float g_k   [16 *  80 * 200];   // key encoder out
__device__ float g_q1  [16 * 160 * 800];   // query conv1 out
__device__ float g_qf  [16 *  80 * 800];   // query encoder out
__device__ float g_kw1T[768 * 512];        // kw1 transposed [(ci*3+k)][co]
__device__ float g_qw1T[240 * 160];
__device__ float g_kw2T[512 *  80];        // kw2 transposed [ci][co]
__device__ float g_qw2T[160 *  80];
__device__ float g_qw3T[ 80 *  80];

// ---------------- packed fp32x2 FMA (Blackwell) ---------------------------
__device__ __forceinline__ float2 ffma2(float2 a, float2 b, float2 c) {
    unsigned long long ua = *reinterpret_cast<unsigned long long*>(&a);
    unsigned long long ub = *reinterpret_cast<unsigned long long*>(&b);
    unsigned long long uc = *reinterpret_cast<unsigned long long*>(&c);
    unsigned long long ud;
    asm("fma.rn.f32x2 %0, %1, %2, %3;" : "=l"(ud) : "l"(ua), "l"(ub), "l"(uc));
    return *reinterpret_cast<float2*>(&ud);
}
__device__ __forceinline__ float2 dup(float v) { return make_float2(v, v); }

// =================== PREP: transpose all weights ==========================
__global__ void prep_kernel(const float* __restrict__ kw1, const float* __restrict__ qw1,
                            const float* __restrict__ kw2, const float* __restrict__ qw2,
                            const float* __restrict__ qw3,
                            float* __restrict__ kw1T, float* __restrict__ qw1T,
                            float* __restrict__ kw2T, float* __restrict__ qw2T,
                            float* __restrict__ qw3T)
{
    int i = blockIdx.x * 256 + threadIdx.x;
    if (i < 393216) {                    // kw1: (512,256,3)
        int r = i >> 9, co = i & 511;
        int ci = r / 3, k = r - ci * 3;
        kw1T[i] = kw1[(co * 256 + ci) * 3 + k];
        return;
    }
    i -= 393216;
    if (i < 38400) {                     // qw1: (160,80,3)
        int r = i / 160, co = i - r * 160;
        int ci = r / 3, k = r - ci * 3;
        qw1T[i] = qw1[(co * 80 + ci) * 3 + k];
        return;
    }
    i -= 38400;
    if (i < 40960) {                     // kw2: (80,512,1)
        int ci = i / 80, co = i - ci * 80;
        kw2T[i] = kw2[co * 512 + ci];
        return;
    }
    i -= 40960;
    if (i < 12800) {                     // qw2: (80,160,1)
        int ci = i / 80, co = i - ci * 80;
        qw2T[i] = qw2[co * 160 + ci];
        return;
    }
    i -= 12800;
    if (i < 6400) {                      // qw3: (80,80,1)
        int ci = i / 80, co = i - ci * 80;
        qw3T[i] = qw3[co * 80 + ci];
    }
}

// =================== KEY conv3 (256->512, T=200) ==========================
// 256 threads = 32 cg x 8 tg; warp = 32 cg at same tg -> x loads broadcast.
// thread tile 4 co (2 pairs) x 8 t; block tile 128 co x 64 t; ci chunks 32.
// smem: sx[32][68] + sw[32*3][128]
__device__ __forceinline__ void conv3_key_body(
    const float* __restrict__ x, const float* __restrict__ wT,
    const float* __restrict__ bias, float* __restrict__ y,
    int b, int t_tile, int co_tile, float* smem)
{
    float* sx = smem;                // 32*68
    float* sw = smem + 2176;         // 96*128

    const int tid = threadIdx.x;
    const int cg = tid & 31, tg = tid >> 5;
    const int tt = tg * 8, ct = cg * 4;
    const int t0 = t_tile * 64, co0 = co_tile * 128;
    const bool active = (t0 + tt) < 200;

    float2 acc[2][8] = {};

    for (int ci0 = 0; ci0 < 256; ci0 += 32) {
        __syncthreads();
        for (int idx = tid; idx < 32 * 66; idx += 256) {
            int cc = idx / 66, j = idx - cc * 66;
            int t = t0 + j - 1;
            sx[cc * 68 + j] = (t >= 0 && t < 200)
                ? x[((size_t)(b * 256) + ci0 + cc) * 200 + t] : 0.f;
        }
        for (int idx = tid; idx < 96 * 128; idx += 256) {
            int r = idx >> 7, co = idx & 127;
            sw[idx] = wT[(size_t)(ci0 * 3 + r) * 512 + co0 + co];
        }
        __syncthreads();
        if (active) {
            #pragma unroll 8
            for (int cc = 0; cc < 32; cc++) {
                const float* xr = &sx[cc * 68 + tt];
                float4 xa = *(const float4*)xr;
                float4 xb = *(const float4*)(xr + 4);
                float2 xc = *(const float2*)(xr + 8);
                float xs[10] = { xa.x, xa.y, xa.z, xa.w,
                                 xb.x, xb.y, xb.z, xb.w, xc.x, xc.y };
                float2 wk[3][2];
                #pragma unroll
                for (int k = 0; k < 3; k++) {
                    float4 wv = *(const float4*)&sw[(cc * 3 + k) * 128 + ct];
                    wk[k][0] = make_float2(wv.x, wv.y);
                    wk[k][1] = make_float2(wv.z, wv.w);
                }
                #pragma unroll
                for (int u = 0; u < 8; u++) {
                    float2 X0 = dup(xs[u]), X1 = dup(xs[u+1]), X2 = dup(xs[u+2]);
                    #pragma unroll
                    for (int p = 0; p < 2; p++)
                        acc[p][u] = ffma2(wk[0][p], X0,
                                    ffma2(wk[1][p], X1,
                                    ffma2(wk[2][p], X2, acc[p][u])));
                }
            }
        }
    }

    if (active) {   // 200 % 8 == 0, so active => all 8 t in-bounds
        #pragma unroll
        for (int p = 0; p < 2; p++) {
            int co = co0 + ct + 2 * p;
            float2 bv = *(const float2*)&bias[co];
            float4 v0a = { fmaxf(acc[p][0].x + bv.x, 0.f), fmaxf(acc[p][1].x + bv.x, 0.f),
                           fmaxf(acc[p][2].x + bv.x, 0.f), fmaxf(acc[p][3].x + bv.x, 0.f) };
            float4 v0b = { fmaxf(acc[p][4].x + bv.x, 0.f), fmaxf(acc[p][5].x + bv.x, 0.f),
                           fmaxf(acc[p][6].x + bv.x, 0.f), fmaxf(acc[p][7].x + bv.x, 0.f) };
            float4 v1a = { fmaxf(acc[p][0].y + bv.y, 0.f), fmaxf(acc[p][1].y + bv.y, 0.f),
                           fmaxf(acc[p][2].y + bv.y, 0.f), fmaxf(acc[p][3].y + bv.y, 0.f) };
            float4 v1b = { fmaxf(acc[p][4].y + bv.y, 0.f), fmaxf(acc[p][5].y + bv.y, 0.f),
                           fmaxf(acc[p][6].y + bv.y, 0.f), fmaxf(acc[p][7].y + bv.y, 0.f) };
            float* y0 = &y[((size_t)(b * 512) + co    ) * 200 + t0 + tt];
            float* y1 = &y[((size_t)(b * 512) + co + 1) * 200 + t0 + tt];
            *(float4*)(y0)     = v0a;  *(float4*)(y0 + 4) = v0b;
            *(float4*)(y1)     = v1a;  *(float4*)(y1 + 4) = v1b;
        }
    }
}

// =================== QUERY conv3 (80->160, T=800) — round-4 scheme ========
__device__ __forceinline__ void conv3_query_body(
    const float* __restrict__ x, const float* __restrict__ wT,
    const float* __restrict__ bias, float* __restrict__ y,
    int b, int t_tile, float* smem)
{
    constexpr int CPAIRS = 5, COT = 160;
    float* sx = smem;               // 32*68
    float* sw = smem + 2176;        // 96*160

    const int tid = threadIdx.x;
    const int cg = tid & 15, tg = tid >> 4;
    const int tt = tg * 4, ct = cg * 10;
    const int t0 = t_tile * 64;
    const bool active = (t0 + tt) < 800;

    float2 acc[CPAIRS][4] = {};

    for (int ci0 = 0; ci0 < 80; ci0 += 32) {
        const int CC = (80 - ci0 < 32) ? (80 - ci0) : 32;
        __syncthreads();
        for (int idx = tid; idx < CC * 66; idx += 256) {
            int cc = idx / 66, j = idx - cc * 66;
            int t = t0 + j - 1;
            sx[cc * 68 + j] = (t >= 0 && t < 800)
                ? x[((size_t)(b * 80) + ci0 + cc) * 800 + t] : 0.f;
        }
        for (int idx = tid; idx < CC * 3 * COT; idx += 256) {
            int r = idx / COT, co = idx - r * COT;
            sw[idx] = wT[(size_t)(ci0 * 3 + r) * 160 + co];
        }
        __syncthreads();
        if (active) {
            #pragma unroll 8
            for (int cc = 0; cc < CC; cc++) {
                const float* xr = &sx[cc * 68 + tt];
                float4 xa = *(const float4*)xr;
                float2 xb = *(const float2*)(xr + 4);
                float2 xv[6] = { dup(xa.x), dup(xa.y), dup(xa.z),
                                 dup(xa.w), dup(xb.x), dup(xb.y) };
                float2 wk[3][CPAIRS];
                #pragma unroll
                for (int k = 0; k < 3; k++) {
                    const float* wb = &sw[(cc * 3 + k) * COT + ct];
                    #pragma unroll
                    for (int p = 0; p < CPAIRS; p++)
                        wk[k][p] = *(const float2*)(wb + 2 * p);
                }
                #pragma unroll
                for (int u = 0; u < 4; u++)
                    #pragma unroll
                    for (int p = 0; p < CPAIRS; p++)
                        acc[p][u] = ffma2(wk[0][p], xv[u],
                                    ffma2(wk[1][p], xv[u+1],
                                    ffma2(wk[2][p], xv[u+2], acc[p][u])));
            }
        }
    }

    if (active) {
        #pragma unroll
        for (int p = 0; p < CPAIRS; p++) {
            int co = ct + 2 * p;
            float2 bv = *(const float2*)&bias[co];
            float4 v0 = { fmaxf(acc[p][0].x + bv.x, 0.f), fmaxf(acc[p][1].x + bv.x, 0.f),
                          fmaxf(acc[p][2].x + bv.x, 0.f), fmaxf(acc[p][3].x + bv.x, 0.f) };
            float4 v1 = { fmaxf(acc[p][0].y + bv.y, 0.f), fmaxf(acc[p][1].y + bv.y, 0.f),
                          fmaxf(acc[p][2].y + bv.y, 0.f), fmaxf(acc[p][3].y + bv.y, 0.f) };
            *(float4*)&y[((size_t)(b * 160) + co    ) * 800 + t0 + tt] = v0;
            *(float4*)&y[((size_t)(b * 160) + co + 1) * 800 + t0 + tt] = v1;
        }
    }
}

__global__ void stageA_kernel(
    const float* __restrict__ keys, const float* __restrict__ kb1,
    const float* __restrict__ queries, const float* __restrict__ qb1,
    float* __restrict__ k1out, float* __restrict__ q1out)
{
    extern __shared__ float smem[];
    int id = blockIdx.x;
    if (id < 256) {
        int r = id & 15;
        conv3_key_body(keys, g_kw1T, kb1, k1out, id >> 4, r >> 2, r & 3, smem);
    } else {
        int j = id - 256;
        conv3_query_body(queries, g_qw1T, qb1, q1out, j / 13, j % 13, smem);
    }
}

// =================== STAGE B: key 1x1 + query 1x1 chain ===================
__device__ __forceinline__ void fma1x1_chunk(
    const float* __restrict__ sx, const float* __restrict__ sw,
    int tt, int cb, int CC, float2 acc[5][4])
{
    #pragma unroll 8
    for (int cc = 0; cc < CC; cc++) {
        float4 xq = *(const float4*)&sx[cc * 128 + tt];
        float2 xv[4] = { dup(xq.x), dup(xq.y), dup(xq.z), dup(xq.w) };
        const float2* wp = (const float2*)&sw[cc * 80 + cb];
        #pragma unroll
        for (int p = 0; p < 5; p++) {
            float2 wd = wp[p];
            #pragma unroll
            for (int u = 0; u < 4; u++)
                acc[p][u] = ffma2(wd, xv[u], acc[p][u]);
        }
    }
}

__device__ __forceinline__ void key1x1_body(
    const float* __restrict__ x, const float* __restrict__ wT,
    const float* __restrict__ bias, float* __restrict__ y,
    int b, int t_tile, float* smem)
{
    float* sx = smem;          // 32*128
    float* sw = smem + 4096;   // 32*80
    const int tid = threadIdx.x;
    const int cg = tid & 7, tg = tid >> 3;
    const int tt = tg * 4, cb = cg * 10;
    const int t0 = t_tile * 128;
    const bool active = (t0 + tt) < 200;
    float2 acc[5][4] = {};

    for (int ci0 = 0; ci0 < 512; ci0 += 32) {
        __syncthreads();
        for (int idx = tid; idx < 4096; idx += 256) {
            int cc = idx >> 7, j = idx & 127;
            int t = t0 + j;
            sx[idx] = (t < 200) ? x[((size_t)(b * 512) + ci0 + cc) * 200 + t] : 0.f;
        }
        for (int idx = tid; idx < 2560; idx += 256)
            sw[idx] = wT[(size_t)ci0 * 80 + idx];
        __syncthreads();
        if (active) fma1x1_chunk(sx, sw, tt, cb, 32, acc);
    }
    if (active) {
        #pragma unroll
        for (int p = 0; p < 5; p++) {
            int co = cb + 2 * p;
            float2 bv = *(const float2*)&bias[co];
            float4 v0 = { acc[p][0].x + bv.x, acc[p][1].x + bv.x,
                          acc[p][2].x + bv.x, acc[p][3].x + bv.x };
            float4 v1 = { acc[p][0].y + bv.y, acc[p][1].y + bv.y,
                          acc[p][2].y + bv.y, acc[p][3].y + bv.y };
            *(float4*)&y[((size_t)(b * 80) + co    ) * 200 + t0 + tt] = v0;
            *(float4*)&y[((size_t)(b * 80) + co + 1) * 200 + t0 + tt] = v1;
        }
    }
}

__device__ __forceinline__ void qchain_body(
    const float* __restrict__ x, const float* __restrict__ w2T, const float* __restrict__ b2,
    const float* __restrict__ w3T, const float* __restrict__ b3,
    float* __restrict__ y, int b, int t_tile, float* smem)
{
    float* sx  = smem;          // 32*128
    float* sw  = smem + 4096;   // 32*80
    float* sh2 = smem + 6656;   // 80*128
    const int tid = threadIdx.x;
    const int cg = tid & 7, tg = tid >> 3;
    const int tt = tg * 4, cb = cg * 10;
    const int t0 = t_tile * 128;
    const bool active = (t0 + tt) < 800;

    {
        float2 acc[5][4] = {};
        for (int ci0 = 0; ci0 < 160; ci0 += 32) {
            __syncthreads();
            for (int idx = tid; idx < 4096; idx += 256) {
                int cc = idx >> 7, j = idx & 127;
                int t = t0 + j;
                sx[idx] = (t < 800) ? x[((size_t)(b * 160) + ci0 + cc) * 800 + t] : 0.f;
            }
            for (int idx = tid; idx < 2560; idx += 256)
                sw[idx] = w2T[(size_t)ci0 * 80 + idx];
            __syncthreads();
            if (active) fma1x1_chunk(sx, sw, tt, cb, 32, acc);
        }
        if (active) {
            #pragma unroll
            for (int p = 0; p < 5; p++) {
                int co = cb + 2 * p;
                float2 bv = *(const float2*)&b2[co];
                float4 v0 = { fmaxf(acc[p][0].x + bv.x, 0.f), fmaxf(acc[p][1].x + bv.x, 0.f),
                              fmaxf(acc[p][2].x + bv.x, 0.f), fmaxf(acc[p][3].x + bv.x, 0.f) };
                float4 v1 = { fmaxf(acc[p][0].y + bv.y, 0.f), fmaxf(acc[p][1].y + bv.y, 0.f),
                              fmaxf(acc[p][2].y + bv.y, 0.f), fmaxf(acc[p][3].y + bv.y, 0.f) };
                *(float4*)&sh2[(co    ) * 128 + tt] = v0;
                *(float4*)&sh2[(co + 1) * 128 + tt] = v1;
            }
        }
    }
    {
        float2 acc[5][4] = {};
        for (int ci0 = 0; ci0 < 80; ci0 += 32) {
            const int CC = (80 - ci0 < 32) ? (80 - ci0) : 32;
            __syncthreads();
            for (int idx = tid; idx < CC * 80; idx += 256)
                sw[idx] = w3T[(size_t)ci0 * 80 + idx];
            __syncthreads();
            if (active) fma1x1_chunk(&sh2[ci0 * 128], sw, tt, cb, CC, acc);
        }
        if (active) {
            #pragma unroll
            for (int p = 0; p < 5; p++) {
                int co = cb + 2 * p;
                float2 bv = *(const float2*)&b3[co];
                float4 v0 = { acc[p][0].x + bv.x, acc[p][1].x + bv.x,
                              acc[p][2].x + bv.x, acc[p][3].x + bv.x };
                float4 v1 = { acc[p][0].y + bv.y, acc[p][1].y + bv.y,
                              acc[p][2].y + bv.y, acc[p][3].y + bv.y };
                *(float4*)&y[((size_t)(b * 80) + co    ) * 800 + t0 + tt] = v0;
                *(float4*)&y[((size_t)(b * 80) + co + 1) * 800 + t0 + tt] = v1;
            }
        }
    }
}

__global__ void stageB_kernel(
    const float* __restrict__ k1in, const float* __restrict__ kb2, float* __restrict__ kout,
    const float* __restrict__ q1in, const float* __restrict__ qb2,
    const float* __restrict__ qb3, float* __restrict__ qout)
{
    extern __shared__ float smem[];
    int id = blockIdx.x;
    if (id < 32) key1x1_body(k1in, g_kw2T, kb2, kout, id >> 1, id & 1, smem);
    else {
        int j = id - 32;
        qchain_body(q1in, g_qw2T, qb2, g_qw3T, qb3, qout, j / 7, j % 7, smem);
    }
}

// =================== STAGE C: L2-dist + log_softmax + log(prior) ==========
// block 256, t1 tile 32, grid (25,16).
// GEMM: thread tile 4s x 8j; sg=tid&63 (<50 active), jg=tid>>6.
// smem: sk[80][200] + sq[80][32] + sq2[32] + sk2[200] + sd[32][200]
__global__ void attention_kernel(const float* __restrict__ q, const float* __restrict__ k,
                                 const float* __restrict__ prior, float* __restrict__ out)
{
    extern __shared__ float smem[];
    float* sk  = smem;                  // 16000
    float* sq  = sk + 16000;            // 2560
    float* sq2 = sq + 2560;             // 32
    float* sk2 = sq2 + 32;              // 200
    float* sd  = sk2 + 200;             // 6400

    const int b    = blockIdx.y;
    const int t1_0 = blockIdx.x * 32;
    const int tid  = threadIdx.x;

    for (int idx = tid; idx < 16000; idx += 256)
        sk[idx] = k[(size_t)b * 16000 + idx];
    for (int idx = tid; idx < 2560; idx += 256) {
        int c = idx >> 5, j = idx & 31;
        sq[idx] = q[((size_t)b * 80 + c) * 800 + t1_0 + j];
    }
    __syncthreads();

    if (tid < 200) {                     // ||k||^2 per s
        float s = 0.f;
        #pragma unroll 8
        for (int c = 0; c < 80; c++) { float v = sk[c * 200 + tid]; s = fmaf(v, v, s); }
        sk2[tid] = s;
    } else if (tid >= 224) {             // ||q||^2 per t1 row (parallel warp)
        int j = tid - 224;
        float s = 0.f;
        #pragma unroll 8
        for (int c = 0; c < 80; c++) { float v = sq[c * 32 + j]; s = fmaf(v, v, s); }
        sq2[j] = s;
    }
    __syncthreads();

    const int sg = tid & 63, jg = tid >> 6;
    if (sg < 50) {
        const int s0 = sg * 4, j0 = jg * 8;
        float2 acc[4][4] = {};           // [si][jpair]
        #pragma unroll 4
        for (int c = 0; c < 80; c++) {
            float4 kq = *(const float4*)&sk[c * 200 + s0];
            float4 qa = *(const float4*)&sq[c * 32 + j0];
            float4 qb = *(const float4*)&sq[c * 32 + j0 + 4];
            float2 qp[4] = { {qa.x,qa.y},{qa.z,qa.w},{qb.x,qb.y},{qb.z,qb.w} };
            float  ks[4] = { kq.x, kq.y, kq.z, kq.w };
            #pragma unroll
            for (int si = 0; si < 4; si++) {
                float2 kd = dup(ks[si]);
                #pragma unroll
                for (int p = 0; p < 4; p++)
                    acc[si][p] = ffma2(kd, qp[p], acc[si][p]);
            }
        }
        float k2v[4] = { sk2[s0], sk2[s0+1], sk2[s0+2], sk2[s0+3] };
        #pragma unroll
        for (int p = 0; p < 4; p++) {
            int ja = j0 + 2 * p, jb = ja + 1;
            float q2a = sq2[ja], q2b = sq2[jb];
            float4 da = { -0.0005f * (q2a + k2v[0] - 2.f * acc[0][p].x),
                          -0.0005f * (q2a + k2v[1] - 2.f * acc[1][p].x),
                          -0.0005f * (q2a + k2v[2] - 2.f * acc[2][p].x),
                          -0.0005f * (q2a + k2v[3] - 2.f * acc[3][p].x) };
            float4 db = { -0.0005f * (q2b + k2v[0] - 2.f * acc[0][p].y),
                          -0.0005f * (q2b + k2v[1] - 2.f * acc[1][p].y),
                          -0.0005f * (q2b + k2v[2] - 2.f * acc[2][p].y),
                          -0.0005f * (q2b + k2v[3] - 2.f * acc[3][p].y) };
            *(float4*)&sd[ja * 200 + s0] = da;
            *(float4*)&sd[jb * 200 + s0] = db;
        }
    }
    __syncthreads();

    const int warp = tid >> 5, lane = tid & 31;
    for (int j = warp; j < 32; j += 8) {
        float m = -1e30f;
        for (int s = lane; s < 200; s += 32) m = fmaxf(m, sd[j * 200 + s]);
        #pragma unroll
        for (int o = 16; o; o >>= 1) m = fmaxf(m, __shfl_xor_sync(0xffffffffu, m, o));
        float sum = 0.f;
        for (int s = lane; s < 200; s += 32) sum += expf(sd[j * 200 + s] - m);
        #pragma unroll
        for (int o = 16; o; o >>= 1) sum += __shfl_xor_sync(0xffffffffu, sum, o);
        float lse = m + logf(sum);
        const float* pr = &prior[((size_t)b * 800 + t1_0 + j) * 200];
        float*       op = &out  [((size_t)b * 800 + t1_0 + j) * 200];
        for (int s = lane; s < 200; s += 32)
            op[s] = sd[j * 200 + s] - lse + logf(pr[s] + 1e-8f);
    }
}

// -------------------------------- launch ---------------------------------
extern "C" void kernel_launch(void* const* d_in, const int* in_sizes, int n_in,
                              void* d_out, int out_size)
{
    const float* queries = (const float*)d_in[0];
    const float* keys    = (const float*)d_in[1];
    const float* prior   = (const float*)d_in[2];
    const float* kw1 = (const float*)d_in[3];
    const float* kb1 = (const float*)d_in[4];
    const float* kw2 = (const float*)d_in[5];
    const float* kb2 = (const float*)d_in[6];
    const float* qw1 = (const float*)d_in[7];
    const float* qb1 = (const float*)d_in[8];
    const float* qw2 = (const float*)d_in[9];
    const float* qb2 = (const float*)d_in[10];
    const float* qw3 = (const float*)d_in[11];
    const float* qb3 = (const float*)d_in[12];
    float* out = (float*)d_out;

    float *k1buf, *kbuf, *q1buf, *qbuf;
    float *kw1T, *qw1T, *kw2T, *qw2T, *qw3T;
    cudaGetSymbolAddress((void**)&k1buf, g_k1);
    cudaGetSymbolAddress((void**)&kbuf,  g_k);
    cudaGetSymbolAddress((void**)&q1buf, g_q1);
    cudaGetSymbolAddress((void**)&qbuf,  g_qf);
    cudaGetSymbolAddress((void**)&kw1T, g_kw1T);
    cudaGetSymbolAddress((void**)&qw1T, g_qw1T);
    cudaGetSymbolAddress((void**)&kw2T, g_kw2T);
    cudaGetSymbolAddress((void**)&qw2T, g_qw2T);
    cudaGetSymbolAddress((void**)&qw3T, g_qw3T);

    const int smem_A    = (32 * 68 + 96 * 160) * 4;                    // 70144
    const int smem_B    = (4096 + 2560 + 80 * 128) * 4;                // 67584
    const int smem_attn = (16000 + 2560 + 32 + 200 + 6400) * 4;        // 100768

    cudaFuncSetAttribute((const void*)stageA_kernel,
                         cudaFuncAttributeMaxDynamicSharedMemorySize, smem_A);
    cudaFuncSetAttribute((const void*)stageB_kernel,
                         cudaFuncAttributeMaxDynamicSharedMemorySize, smem_B);
    cudaFuncSetAttribute((const void*)attention_kernel,
                         cudaFuncAttributeMaxDynamicSharedMemorySize, smem_attn);

    prep_kernel<<<1921, 256>>>(kw1, qw1, kw2, qw2, qw3, kw1T, qw1T, kw2T, qw2T, qw3T);
    stageA_kernel<<<464, 256, smem_A>>>(keys, kb1, queries, qb1, k1buf, q1buf);
    stageB_kernel<<<144, 256, smem_B>>>(k1buf, kb2, kbuf, q1buf, qb2, qb3, qbuf);
    attention_kernel<<<dim3(25, 16), 256, smem_attn>>>(qbuf, kbuf, prior, out);
}

// round 6
// speedup vs baseline: 1.3806x; 1.3806x over previous
#include <cuda_runtime.h>
#include <math.h>

// ---------------- scratch (device globals; no allocation) ----------------
__device__ float g_k1  [16 * 512 * 200];   // key conv1 out
__device__ float g_k   [16 *  80 * 200];   // key encoder out
__device__ float g_q1  [16 * 160 * 800];   // query conv1 out
__device__ float g_qf  [16 *  80 * 800];   // query encoder out
__device__ float g_kw1T[768 * 512];        // kw1 transposed [(ci*3+k)][co]
__device__ float g_qw1T[240 * 160];
__device__ float g_kw2T[512 *  80];        // kw2 transposed [ci][co]
__device__ float g_qw2T[160 *  80];
__device__ float g_qw3T[ 80 *  80];

// ---------------- packed fp32x2 FMA (Blackwell) ---------------------------
__device__ __forceinline__ float2 ffma2(float2 a, float2 b, float2 c) {
    unsigned long long ua = *reinterpret_cast<unsigned long long*>(&a);
    unsigned long long ub = *reinterpret_cast<unsigned long long*>(&b);
    unsigned long long uc = *reinterpret_cast<unsigned long long*>(&c);
    unsigned long long ud;
    asm("fma.rn.f32x2 %0, %1, %2, %3;" : "=l"(ud) : "l"(ua), "l"(ub), "l"(uc));
    return *reinterpret_cast<float2*>(&ud);
}
__device__ __forceinline__ float2 dup(float v) { return make_float2(v, v); }

// =================== PREP: transpose all weights ==========================
__global__ void prep_kernel(const float* __restrict__ kw1, const float* __restrict__ qw1,
                            const float* __restrict__ kw2, const float* __restrict__ qw2,
                            const float* __restrict__ qw3,
                            float* __restrict__ kw1T, float* __restrict__ qw1T,
                            float* __restrict__ kw2T, float* __restrict__ qw2T,
                            float* __restrict__ qw3T)
{
    int i = blockIdx.x * 256 + threadIdx.x;
    if (i < 393216) {                    // kw1: (512,256,3)
        int r = i >> 9, co = i & 511;
        int ci = r / 3, k = r - ci * 3;
        kw1T[i] = kw1[(co * 256 + ci) * 3 + k];
        return;
    }
    i -= 393216;
    if (i < 38400) {                     // qw1: (160,80,3)
        int r = i / 160, co = i - r * 160;
        int ci = r / 3, k = r - ci * 3;
        qw1T[i] = qw1[(co * 80 + ci) * 3 + k];
        return;
    }
    i -= 38400;
    if (i < 40960) {                     // kw2: (80,512,1)
        int ci = i / 80, co = i - ci * 80;
        kw2T[i] = kw2[co * 512 + ci];
        return;
    }
    i -= 40960;
    if (i < 12800) {                     // qw2: (80,160,1)
        int ci = i / 80, co = i - ci * 80;
        qw2T[i] = qw2[co * 160 + ci];
        return;
    }
    i -= 12800;
    if (i < 6400) {                      // qw3: (80,80,1)
        int ci = i / 80, co = i - ci * 80;
        qw3T[i] = qw3[co * 80 + ci];
    }
}

// =================== STAGE A: both k=3 pad=1 convs ========================
// 256 threads = 16 cg x 16 tg; thread tile = (2*CPAIRS) co x 4 t (co-paired f32x2).
// block tile = 32*CPAIRS co x 64 t.  ci chunks of 32.
// smem: sx[32][68] + sw[32*3][COT]
template<int CIN, int COUT, int TLEN, int CPAIRS>
__device__ __forceinline__ void conv3_body(
    const float* __restrict__ x, const float* __restrict__ wT,
    const float* __restrict__ bias, float* __restrict__ y,
    int b, int t_tile, int co_tile, float* smem)
{
    constexpr int COT = 32 * CPAIRS;
    float* sx = smem;               // 32*68
    float* sw = smem + 32 * 68;     // 32*3*COT

    const int tid = threadIdx.x;
    const int cg = tid & 15, tg = tid >> 4;
    const int tt = tg * 4, ct = cg * 2 * CPAIRS;
    const int t0 = t_tile * 64, co0 = co_tile * COT;
    const bool active = (t0 + tt) < TLEN;

    float2 acc[CPAIRS][4] = {};

    for (int ci0 = 0; ci0 < CIN; ci0 += 32) {
        const int CC = (CIN - ci0 < 32) ? (CIN - ci0) : 32;
        __syncthreads();
        for (int idx = tid; idx < CC * 66; idx += 256) {
            int cc = idx / 66, j = idx - cc * 66;
            int t = t0 + j - 1;
            sx[cc * 68 + j] = (t >= 0 && t < TLEN)
                ? x[((size_t)(b * CIN) + ci0 + cc) * TLEN + t] : 0.f;
        }
        for (int idx = tid; idx < CC * 3 * COT; idx += 256) {
            int r = idx / COT, co = idx - r * COT;
            sw[idx] = wT[(size_t)(ci0 * 3 + r) * COUT + co0 + co];
        }
        __syncthreads();
        if (active) {
            #pragma unroll 8
            for (int cc = 0; cc < CC; cc++) {
                const float* xr = &sx[cc * 68 + tt];
                float4 xa = *(const float4*)xr;
                float2 xb = *(const float2*)(xr + 4);
                float2 xv[6] = { dup(xa.x), dup(xa.y), dup(xa.z),
                                 dup(xa.w), dup(xb.x), dup(xb.y) };
                float2 wk[3][CPAIRS];
                #pragma unroll
                for (int k = 0; k < 3; k++) {
                    const float* wb = &sw[(cc * 3 + k) * COT + ct];
                    if constexpr ((CPAIRS & 1) == 0) {
                        #pragma unroll
                        for (int q = 0; q < CPAIRS / 2; q++) {
                            float4 wv = *(const float4*)(wb + 4 * q);
                            wk[k][2*q]   = make_float2(wv.x, wv.y);
                            wk[k][2*q+1] = make_float2(wv.z, wv.w);
                        }
                    } else {
                        #pragma unroll
                        for (int p = 0; p < CPAIRS; p++)
                            wk[k][p] = *(const float2*)(wb + 2 * p);
                    }
                }
                #pragma unroll
                for (int u = 0; u < 4; u++)
                    #pragma unroll
                    for (int p = 0; p < CPAIRS; p++)
                        acc[p][u] = ffma2(wk[0][p], xv[u],
                                    ffma2(wk[1][p], xv[u+1],
                                    ffma2(wk[2][p], xv[u+2], acc[p][u])));
            }
        }
    }

    if (active) {
        #pragma unroll
        for (int p = 0; p < CPAIRS; p++) {
            int co = co0 + ct + 2 * p;
            float2 bv = *(const float2*)&bias[co];
            float4 v0 = { fmaxf(acc[p][0].x + bv.x, 0.f), fmaxf(acc[p][1].x + bv.x, 0.f),
                          fmaxf(acc[p][2].x + bv.x, 0.f), fmaxf(acc[p][3].x + bv.x, 0.f) };
            float4 v1 = { fmaxf(acc[p][0].y + bv.y, 0.f), fmaxf(acc[p][1].y + bv.y, 0.f),
                          fmaxf(acc[p][2].y + bv.y, 0.f), fmaxf(acc[p][3].y + bv.y, 0.f) };
            *(float4*)&y[((size_t)(b * COUT) + co    ) * TLEN + t0 + tt] = v0;
            *(float4*)&y[((size_t)(b * COUT) + co + 1) * TLEN + t0 + tt] = v1;
        }
    }
}

__global__ void stageA_kernel(
    const float* __restrict__ keys, const float* __restrict__ kb1,
    const float* __restrict__ queries, const float* __restrict__ qb1,
    float* __restrict__ k1out, float* __restrict__ q1out)
{
    extern __shared__ float smem[];
    int id = blockIdx.x;
    if (id < 256) {
        int r = id & 15;
        conv3_body<256, 512, 200, 4>(keys, g_kw1T, kb1, k1out,
                                     id >> 4, r & 3, r >> 2, smem);
    } else {
        int j = id - 256;
        conv3_body<80, 160, 800, 5>(queries, g_qw1T, qb1, q1out,
                                    j / 13, j % 13, 0, smem);
    }
}

// =================== STAGE B: key 1x1 + query 1x1 chain ===================
__device__ __forceinline__ void fma1x1_chunk(
    const float* __restrict__ sx, const float* __restrict__ sw,
    int tt, int cb, int CC, float2 acc[5][4])
{
    #pragma unroll 8
    for (int cc = 0; cc < CC; cc++) {
        float4 xq = *(const float4*)&sx[cc * 128 + tt];
        float2 xv[4] = { dup(xq.x), dup(xq.y), dup(xq.z), dup(xq.w) };
        const float2* wp = (const float2*)&sw[cc * 80 + cb];
        #pragma unroll
        for (int p = 0; p < 5; p++) {
            float2 wd = wp[p];
            #pragma unroll
            for (int u = 0; u < 4; u++)
                acc[p][u] = ffma2(wd, xv[u], acc[p][u]);
        }
    }
}

__device__ __forceinline__ void key1x1_body(
    const float* __restrict__ x, const float* __restrict__ wT,
    const float* __restrict__ bias, float* __restrict__ y,
    int b, int t_tile, float* smem)
{
    float* sx = smem;          // 32*128
    float* sw = smem + 4096;   // 32*80
    const int tid = threadIdx.x;
    const int cg = tid & 7, tg = tid >> 3;
    const int tt = tg * 4, cb = cg * 10;
    const int t0 = t_tile * 128;
    const bool active = (t0 + tt) < 200;
    float2 acc[5][4] = {};

    for (int ci0 = 0; ci0 < 512; ci0 += 32) {
        __syncthreads();
        for (int idx = tid; idx < 4096; idx += 256) {
            int cc = idx >> 7, j = idx & 127;
            int t = t0 + j;
            sx[idx] = (t < 200) ? x[((size_t)(b * 512) + ci0 + cc) * 200 + t] : 0.f;
        }
        for (int idx = tid; idx < 2560; idx += 256)
            sw[idx] = wT[(size_t)ci0 * 80 + idx];
        __syncthreads();
        if (active) fma1x1_chunk(sx, sw, tt, cb, 32, acc);
    }
    if (active) {
        #pragma unroll
        for (int p = 0; p < 5; p++) {
            int co = cb + 2 * p;
            float2 bv = *(const float2*)&bias[co];
            float4 v0 = { acc[p][0].x + bv.x, acc[p][1].x + bv.x,
                          acc[p][2].x + bv.x, acc[p][3].x + bv.x };
            float4 v1 = { acc[p][0].y + bv.y, acc[p][1].y + bv.y,
                          acc[p][2].y + bv.y, acc[p][3].y + bv.y };
            *(float4*)&y[((size_t)(b * 80) + co    ) * 200 + t0 + tt] = v0;
            *(float4*)&y[((size_t)(b * 80) + co + 1) * 200 + t0 + tt] = v1;
        }
    }
}

__device__ __forceinline__ void qchain_body(
    const float* __restrict__ x, const float* __restrict__ w2T, const float* __restrict__ b2,
    const float* __restrict__ w3T, const float* __restrict__ b3,
    float* __restrict__ y, int b, int t_tile, float* smem)
{
    float* sx  = smem;          // 32*128
    float* sw  = smem + 4096;   // 32*80
    float* sh2 = smem + 6656;   // 80*128
    const int tid = threadIdx.x;
    const int cg = tid & 7, tg = tid >> 3;
    const int tt = tg * 4, cb = cg * 10;
    const int t0 = t_tile * 128;
    const bool active = (t0 + tt) < 800;

    {   // phase 1: h2 = relu(W2 x + b2), CIN=160 -> sh2
        float2 acc[5][4] = {};
        for (int ci0 = 0; ci0 < 160; ci0 += 32) {
            __syncthreads();
            for (int idx = tid; idx < 4096; idx += 256) {
                int cc = idx >> 7, j = idx & 127;
                int t = t0 + j;
                sx[idx] = (t < 800) ? x[((size_t)(b * 160) + ci0 + cc) * 800 + t] : 0.f;
            }
            for (int idx = tid; idx < 2560; idx += 256)
                sw[idx] = w2T[(size_t)ci0 * 80 + idx];
            __syncthreads();
            if (active) fma1x1_chunk(sx, sw, tt, cb, 32, acc);
        }
        if (active) {
            #pragma unroll
            for (int p = 0; p < 5; p++) {
                int co = cb + 2 * p;
                float2 bv = *(const float2*)&b2[co];
                float4 v0 = { fmaxf(acc[p][0].x + bv.x, 0.f), fmaxf(acc[p][1].x + bv.x, 0.f),
                              fmaxf(acc[p][2].x + bv.x, 0.f), fmaxf(acc[p][3].x + bv.x, 0.f) };
                float4 v1 = { fmaxf(acc[p][0].y + bv.y, 0.f), fmaxf(acc[p][1].y + bv.y, 0.f),
                              fmaxf(acc[p][2].y + bv.y, 0.f), fmaxf(acc[p][3].y + bv.y, 0.f) };
                *(float4*)&sh2[(co    ) * 128 + tt] = v0;
                *(float4*)&sh2[(co + 1) * 128 + tt] = v1;
            }
        }
    }
    {   // phase 2: q = W3 h2 + b3, CIN=80 (h2 in smem)
        float2 acc[5][4] = {};
        for (int ci0 = 0; ci0 < 80; ci0 += 32) {
            const int CC = (80 - ci0 < 32) ? (80 - ci0) : 32;
            __syncthreads();
            for (int idx = tid; idx < CC * 80; idx += 256)
                sw[idx] = w3T[(size_t)ci0 * 80 + idx];
            __syncthreads();
            if (active) fma1x1_chunk(&sh2[ci0 * 128], sw, tt, cb, CC, acc);
        }
        if (active) {
            #pragma unroll
            for (int p = 0; p < 5; p++) {
                int co = cb + 2 * p;
                float2 bv = *(const float2*)&b3[co];
                float4 v0 = { acc[p][0].x + bv.x, acc[p][1].x + bv.x,
                              acc[p][2].x + bv.x, acc[p][3].x + bv.x };
                float4 v1 = { acc[p][0].y + bv.y, acc[p][1].y + bv.y,
                              acc[p][2].y + bv.y, acc[p][3].y + bv.y };
                *(float4*)&y[((size_t)(b * 80) + co    ) * 800 + t0 + tt] = v0;
                *(float4*)&y[((size_t)(b * 80) + co + 1) * 800 + t0 + tt] = v1;
            }
        }
    }
}

__global__ void stageB_kernel(
    const float* __restrict__ k1in, const float* __restrict__ kb2, float* __restrict__ kout,
    const float* __restrict__ q1in, const float* __restrict__ qb2,
    const float* __restrict__ qb3, float* __restrict__ qout)
{
    extern __shared__ float smem[];
    int id = blockIdx.x;
    if (id < 32) key1x1_body(k1in, g_kw2T, kb2, kout, id >> 1, id & 1, smem);
    else {
        int j = id - 32;
        qchain_body(q1in, g_qw2T, qb2, g_qw3T, qb3, qout, j / 7, j % 7, smem);
    }
}

// =================== STAGE C: L2-dist + log_softmax + log(prior) ==========
// identical structure to the 252.7us version; only expf/logf -> __expf/__logf
__global__ void attention_kernel(const float* __restrict__ q, const float* __restrict__ k,
                                 const float* __restrict__ prior, float* __restrict__ out)
{
    extern __shared__ float smem[];
    float* sk  = smem;                  // 80*200
    float* sq  = sk + 16000;            // 80*32
    float* sq2 = sq + 2560;             // 32
    float* sd  = sq2 + 32;              // 32*200

    const int b    = blockIdx.y;
    const int t1_0 = blockIdx.x * 32;
    const int tid  = threadIdx.x;

    for (int idx = tid; idx < 16000; idx += 256)
        sk[idx] = k[(size_t)b * 16000 + idx];
    for (int idx = tid; idx < 2560; idx += 256) {
        int c = idx >> 5, j = idx & 31;
        sq[idx] = q[((size_t)b * 80 + c) * 800 + t1_0 + j];
    }
    __syncthreads();

    if (tid < 32) {
        float s = 0.f;
        #pragma unroll 8
        for (int c = 0; c < 80; c++) { float v = sq[c * 32 + tid]; s = fmaf(v, v, s); }
        sq2[tid] = s;
    }
    __syncthreads();

    if (tid < 200) {
        float2 acc[16] = {};
        float k2 = 0.f;
        #pragma unroll 4
        for (int c = 0; c < 80; c++) {
            float kc = sk[c * 200 + tid];
            float2 kd = make_float2(kc, kc);
            k2 = fmaf(kc, kc, k2);
            const float4* qr = (const float4*)&sq[c * 32];
            #pragma unroll
            for (int jj = 0; jj < 8; jj++) {
                float4 qv = qr[jj];
                acc[2*jj]   = ffma2(kd, make_float2(qv.x, qv.y), acc[2*jj]);
                acc[2*jj+1] = ffma2(kd, make_float2(qv.z, qv.w), acc[2*jj+1]);
            }
        }
        #pragma unroll
        for (int p = 0; p < 16; p++) {
            int j = 2 * p;
            sd[j * 200 + tid]       = -0.0005f * (sq2[j]     + k2 - 2.f * acc[p].x);
            sd[(j + 1) * 200 + tid] = -0.0005f * (sq2[j + 1] + k2 - 2.f * acc[p].y);
        }
    }
    __syncthreads();

    const int warp = tid >> 5, lane = tid & 31;
    for (int j = warp; j < 32; j += 8) {
        float m = -1e30f;
        for (int s = lane; s < 200; s += 32) m = fmaxf(m, sd[j * 200 + s]);
        #pragma unroll
        for (int o = 16; o; o >>= 1) m = fmaxf(m, __shfl_xor_sync(0xffffffffu, m, o));
        float sum = 0.f;
        for (int s = lane; s < 200; s += 32) sum += __expf(sd[j * 200 + s] - m);
        #pragma unroll
        for (int o = 16; o; o >>= 1) sum += __shfl_xor_sync(0xffffffffu, sum, o);
        float lse = m + __logf(sum);
        const float* pr = &prior[((size_t)b * 800 + t1_0 + j) * 200];
        float*       op = &out  [((size_t)b * 800 + t1_0 + j) * 200];
        for (int s = lane; s < 200; s += 32)
            op[s] = sd[j * 200 + s] - lse + __logf(pr[s] + 1e-8f);
    }
}

// -------------------------------- launch ---------------------------------
extern "C" void kernel_launch(void* const* d_in, const int* in_sizes, int n_in,
                              void* d_out, int out_size)
{
    const float* queries = (const float*)d_in[0];
    const float* keys    = (const float*)d_in[1];
    const float* prior   = (const float*)d_in[2];
    const float* kw1 = (const float*)d_in[3];
    const float* kb1 = (const float*)d_in[4];
    const float* kw2 = (const float*)d_in[5];
    const float* kb2 = (const float*)d_in[6];
    const float* qw1 = (const float*)d_in[7];
    const float* qb1 = (const float*)d_in[8];
    const float* qw2 = (const float*)d_in[9];
    const float* qb2 = (const float*)d_in[10];
    const float* qw3 = (const float*)d_in[11];
    const float* qb3 = (const float*)d_in[12];
    float* out = (float*)d_out;

    float *k1buf, *kbuf, *q1buf, *qbuf;
    float *kw1T, *qw1T, *kw2T, *qw2T, *qw3T;
    cudaGetSymbolAddress((void**)&k1buf, g_k1);
    cudaGetSymbolAddress((void**)&kbuf,  g_k);
    cudaGetSymbolAddress((void**)&q1buf, g_q1);
    cudaGetSymbolAddress((void**)&qbuf,  g_qf);
    cudaGetSymbolAddress((void**)&kw1T, g_kw1T);
    cudaGetSymbolAddress((void**)&qw1T, g_qw1T);
    cudaGetSymbolAddress((void**)&kw2T, g_kw2T);
    cudaGetSymbolAddress((void**)&qw2T, g_qw2T);
    cudaGetSymbolAddress((void**)&qw3T, g_qw3T);

    const int smem_A    = (32 * 68 + 32 * 3 * 160) * 4;          // 70144
    const int smem_B    = (4096 + 2560 + 80 * 128) * 4;          // 67584
    const int smem_attn = (16000 + 2560 + 32 + 6400) * 4;        // 99968

    cudaFuncSetAttribute((const void*)stageA_kernel,
                         cudaFuncAttributeMaxDynamicSharedMemorySize, smem_A);
    cudaFuncSetAttribute((const void*)stageB_kernel,
                         cudaFuncAttributeMaxDynamicSharedMemorySize, smem_B);
    cudaFuncSetAttribute((const void*)attention_kernel,
                         cudaFuncAttributeMaxDynamicSharedMemorySize, smem_attn);

    prep_kernel<<<1921, 256>>>(kw1, qw1, kw2, qw2, qw3, kw1T, qw1T, kw2T, qw2T, qw3T);
    stageA_kernel<<<464, 256, smem_A>>>(keys, kb1, queries, qb1, k1buf, q1buf);
    stageB_kernel<<<144, 256, smem_B>>>(k1buf, kb2, kbuf, q1buf, qb2, qb3, qbuf);
    attention_kernel<<<dim3(25, 16), 256, smem_attn>>>(qbuf, kbuf, prior, out);
}

// round 7
// speedup vs baseline: 1.5336x; 1.1108x over previous
#include <cuda_runtime.h>
#include <math.h>

// ---------------- scratch (device globals; no allocation) ----------------
__device__ float g_k1  [16 * 512 * 200];   // key conv1 out
__device__ float g_k   [16 *  80 * 200];   // key encoder out
__device__ float g_q1  [16 * 160 * 800];   // query conv1 out
__device__ float g_qf  [16 *  80 * 800];   // query encoder out
__device__ float g_kw1T[768 * 512];        // kw1 transposed [(ci*3+k)][co]
__device__ float g_qw1T[240 * 160];
__device__ float g_kw2T[512 *  80];        // kw2 transposed [ci][co]
__device__ float g_qw2T[160 *  80];
__device__ float g_qw3T[ 80 *  80];

// ---------------- packed fp32x2 FMA (Blackwell) ---------------------------
__device__ __forceinline__ float2 ffma2(float2 a, float2 b, float2 c) {
    unsigned long long ua = *reinterpret_cast<unsigned long long*>(&a);
    unsigned long long ub = *reinterpret_cast<unsigned long long*>(&b);
    unsigned long long uc = *reinterpret_cast<unsigned long long*>(&c);
    unsigned long long ud;
    asm("fma.rn.f32x2 %0, %1, %2, %3;" : "=l"(ud) : "l"(ua), "l"(ub), "l"(uc));
    return *reinterpret_cast<float2*>(&ud);
}
__device__ __forceinline__ float2 dup(float v) { return make_float2(v, v); }

// =================== PREP: transpose all weights ==========================
__global__ void prep_kernel(const float* __restrict__ kw1, const float* __restrict__ qw1,
                            const float* __restrict__ kw2, const float* __restrict__ qw2,
                            const float* __restrict__ qw3,
                            float* __restrict__ kw1T, float* __restrict__ qw1T,
                            float* __restrict__ kw2T, float* __restrict__ qw2T,
                            float* __restrict__ qw3T)
{
    int i = blockIdx.x * 256 + threadIdx.x;
    if (i < 393216) {                    // kw1: (512,256,3)
        int r = i >> 9, co = i & 511;
        int ci = r / 3, k = r - ci * 3;
        kw1T[i] = kw1[(co * 256 + ci) * 3 + k];
        return;
    }
    i -= 393216;
    if (i < 38400) {                     // qw1: (160,80,3)
        int r = i / 160, co = i - r * 160;
        int ci = r / 3, k = r - ci * 3;
        qw1T[i] = qw1[(co * 80 + ci) * 3 + k];
        return;
    }
    i -= 38400;
    if (i < 40960) {                     // kw2: (80,512,1)
        int ci = i / 80, co = i - ci * 80;
        kw2T[i] = kw2[co * 512 + ci];
        return;
    }
    i -= 40960;
    if (i < 12800) {                     // qw2: (80,160,1)
        int ci = i / 80, co = i - ci * 80;
        qw2T[i] = qw2[co * 160 + ci];
        return;
    }
    i -= 12800;
    if (i < 6400) {                      // qw3: (80,80,1)
        int ci = i / 80, co = i - ci * 80;
        qw3T[i] = qw3[co * 80 + ci];
    }
}

// =================== STAGE A: both k=3 pad=1 convs ========================
template<int CIN, int COUT, int TLEN, int CPAIRS>
__device__ __forceinline__ void conv3_body(
    const float* __restrict__ x, const float* __restrict__ wT,
    const float* __restrict__ bias, float* __restrict__ y,
    int b, int t_tile, int co_tile, float* smem)
{
    constexpr int COT = 32 * CPAIRS;
    float* sx = smem;               // 32*68
    float* sw = smem + 32 * 68;     // 32*3*COT

    const int tid = threadIdx.x;
    const int cg = tid & 15, tg = tid >> 4;
    const int tt = tg * 4, ct = cg * 2 * CPAIRS;
    const int t0 = t_tile * 64, co0 = co_tile * COT;
    const bool active = (t0 + tt) < TLEN;

    float2 acc[CPAIRS][4] = {};

    for (int ci0 = 0; ci0 < CIN; ci0 += 32) {
        const int CC = (CIN - ci0 < 32) ? (CIN - ci0) : 32;
        __syncthreads();
        for (int idx = tid; idx < CC * 66; idx += 256) {
            int cc = idx / 66, j = idx - cc * 66;
            int t = t0 + j - 1;
            sx[cc * 68 + j] = (t >= 0 && t < TLEN)
                ? x[((size_t)(b * CIN) + ci0 + cc) * TLEN + t] : 0.f;
        }
        for (int idx = tid; idx < CC * 3 * COT; idx += 256) {
            int r = idx / COT, co = idx - r * COT;
            sw[idx] = wT[(size_t)(ci0 * 3 + r) * COUT + co0 + co];
        }
        __syncthreads();
        if (active) {
            #pragma unroll 8
            for (int cc = 0; cc < CC; cc++) {
                const float* xr = &sx[cc * 68 + tt];
                float4 xa = *(const float4*)xr;
                float2 xb = *(const float2*)(xr + 4);
                float2 xv[6] = { dup(xa.x), dup(xa.y), dup(xa.z),
                                 dup(xa.w), dup(xb.x), dup(xb.y) };
                float2 wk[3][CPAIRS];
                #pragma unroll
                for (int k = 0; k < 3; k++) {
                    const float* wb = &sw[(cc * 3 + k) * COT + ct];
                    if constexpr ((CPAIRS & 1) == 0) {
                        #pragma unroll
                        for (int q = 0; q < CPAIRS / 2; q++) {
                            float4 wv = *(const float4*)(wb + 4 * q);
                            wk[k][2*q]   = make_float2(wv.x, wv.y);
                            wk[k][2*q+1] = make_float2(wv.z, wv.w);
                        }
                    } else {
                        #pragma unroll
                        for (int p = 0; p < CPAIRS; p++)
                            wk[k][p] = *(const float2*)(wb + 2 * p);
                    }
                }
                #pragma unroll
                for (int u = 0; u < 4; u++)
                    #pragma unroll
                    for (int p = 0; p < CPAIRS; p++)
                        acc[p][u] = ffma2(wk[0][p], xv[u],
                                    ffma2(wk[1][p], xv[u+1],
                                    ffma2(wk[2][p], xv[u+2], acc[p][u])));
            }
        }
    }

    if (active) {
        #pragma unroll
        for (int p = 0; p < CPAIRS; p++) {
            int co = co0 + ct + 2 * p;
            float2 bv = *(const float2*)&bias[co];
            float4 v0 = { fmaxf(acc[p][0].x + bv.x, 0.f), fmaxf(acc[p][1].x + bv.x, 0.f),
                          fmaxf(acc[p][2].x + bv.x, 0.f), fmaxf(acc[p][3].x + bv.x, 0.f) };
            float4 v1 = { fmaxf(acc[p][0].y + bv.y, 0.f), fmaxf(acc[p][1].y + bv.y, 0.f),
                          fmaxf(acc[p][2].y + bv.y, 0.f), fmaxf(acc[p][3].y + bv.y, 0.f) };
            *(float4*)&y[((size_t)(b * COUT) + co    ) * TLEN + t0 + tt] = v0;
            *(float4*)&y[((size_t)(b * COUT) + co + 1) * TLEN + t0 + tt] = v1;
        }
    }
}

__global__ void stageA_kernel(
    const float* __restrict__ keys, const float* __restrict__ kb1,
    const float* __restrict__ queries, const float* __restrict__ qb1,
    float* __restrict__ k1out, float* __restrict__ q1out)
{
    extern __shared__ float smem[];
    int id = blockIdx.x;
    if (id < 256) {
        int r = id & 15;
        conv3_body<256, 512, 200, 4>(keys, g_kw1T, kb1, k1out,
                                     id >> 4, r & 3, r >> 2, smem);
    } else {
        int j = id - 256;
        conv3_body<80, 160, 800, 5>(queries, g_qw1T, qb1, q1out,
                                    j / 13, j % 13, 0, smem);
    }
}

// =================== STAGE B: key 1x1 + query 1x1 chain ===================
__device__ __forceinline__ void fma1x1_chunk(
    const float* __restrict__ sx, const float* __restrict__ sw,
    int tt, int cb, int CC, float2 acc[5][4])
{
    #pragma unroll 8
    for (int cc = 0; cc < CC; cc++) {
        float4 xq = *(const float4*)&sx[cc * 128 + tt];
        float2 xv[4] = { dup(xq.x), dup(xq.y), dup(xq.z), dup(xq.w) };
        const float2* wp = (const float2*)&sw[cc * 80 + cb];
        #pragma unroll
        for (int p = 0; p < 5; p++) {
            float2 wd = wp[p];
            #pragma unroll
            for (int u = 0; u < 4; u++)
                acc[p][u] = ffma2(wd, xv[u], acc[p][u]);
        }
    }
}

__device__ __forceinline__ void key1x1_body(
    const float* __restrict__ x, const float* __restrict__ wT,
    const float* __restrict__ bias, float* __restrict__ y,
    int b, int t_tile, float* smem)
{
    float* sx = smem;          // 32*128
    float* sw = smem + 4096;   // 32*80
    const int tid = threadIdx.x;
    const int cg = tid & 7, tg = tid >> 3;
    const int tt = tg * 4, cb = cg * 10;
    const int t0 = t_tile * 128;
    const bool active = (t0 + tt) < 200;
    float2 acc[5][4] = {};

    for (int ci0 = 0; ci0 < 512; ci0 += 32) {
        __syncthreads();
        for (int idx = tid; idx < 4096; idx += 256) {
            int cc = idx >> 7, j = idx & 127;
            int t = t0 + j;
            sx[idx] = (t < 200) ? x[((size_t)(b * 512) + ci0 + cc) * 200 + t] : 0.f;
        }
        for (int idx = tid; idx < 2560; idx += 256)
            sw[idx] = wT[(size_t)ci0 * 80 + idx];
        __syncthreads();
        if (active) fma1x1_chunk(sx, sw, tt, cb, 32, acc);
    }
    if (active) {
        #pragma unroll
        for (int p = 0; p < 5; p++) {
            int co = cb + 2 * p;
            float2 bv = *(const float2*)&bias[co];
            float4 v0 = { acc[p][0].x + bv.x, acc[p][1].x + bv.x,
                          acc[p][2].x + bv.x, acc[p][3].x + bv.x };
            float4 v1 = { acc[p][0].y + bv.y, acc[p][1].y + bv.y,
                          acc[p][2].y + bv.y, acc[p][3].y + bv.y };
            *(float4*)&y[((size_t)(b * 80) + co    ) * 200 + t0 + tt] = v0;
            *(float4*)&y[((size_t)(b * 80) + co + 1) * 200 + t0 + tt] = v1;
        }
    }
}

__device__ __forceinline__ void qchain_body(
    const float* __restrict__ x, const float* __restrict__ w2T, const float* __restrict__ b2,
    const float* __restrict__ w3T, const float* __restrict__ b3,
    float* __restrict__ y, int b, int t_tile, float* smem)
{
    float* sx  = smem;          // 32*128
    float* sw  = smem + 4096;   // 32*80
    float* sh2 = smem + 6656;   // 80*128
    const int tid = threadIdx.x;
    const int cg = tid & 7, tg = tid >> 3;
    const int tt = tg * 4, cb = cg * 10;
    const int t0 = t_tile * 128;
    const bool active = (t0 + tt) < 800;

    {   // phase 1: h2 = relu(W2 x + b2), CIN=160 -> sh2
        float2 acc[5][4] = {};
        for (int ci0 = 0; ci0 < 160; ci0 += 32) {
            __syncthreads();
            for (int idx = tid; idx < 4096; idx += 256) {
                int cc = idx >> 7, j = idx & 127;
                int t = t0 + j;
                sx[idx] = (t < 800) ? x[((size_t)(b * 160) + ci0 + cc) * 800 + t] : 0.f;
            }
            for (int idx = tid; idx < 2560; idx += 256)
                sw[idx] = w2T[(size_t)ci0 * 80 + idx];
            __syncthreads();
            if (active) fma1x1_chunk(sx, sw, tt, cb, 32, acc);
        }
        if (active) {
            #pragma unroll
            for (int p = 0; p < 5; p++) {
                int co = cb + 2 * p;
                float2 bv = *(const float2*)&b2[co];
                float4 v0 = { fmaxf(acc[p][0].x + bv.x, 0.f), fmaxf(acc[p][1].x + bv.x, 0.f),
                              fmaxf(acc[p][2].x + bv.x, 0.f), fmaxf(acc[p][3].x + bv.x, 0.f) };
                float4 v1 = { fmaxf(acc[p][0].y + bv.y, 0.f), fmaxf(acc[p][1].y + bv.y, 0.f),
                              fmaxf(acc[p][2].y + bv.y, 0.f), fmaxf(acc[p][3].y + bv.y, 0.f) };
                *(float4*)&sh2[(co    ) * 128 + tt] = v0;
                *(float4*)&sh2[(co + 1) * 128 + tt] = v1;
            }
        }
    }
    {   // phase 2: q = W3 h2 + b3, CIN=80 (h2 in smem)
        float2 acc[5][4] = {};
        for (int ci0 = 0; ci0 < 80; ci0 += 32) {
            const int CC = (80 - ci0 < 32) ? (80 - ci0) : 32;
            __syncthreads();
            for (int idx = tid; idx < CC * 80; idx += 256)
                sw[idx] = w3T[(size_t)ci0 * 80 + idx];
            __syncthreads();
            if (active) fma1x1_chunk(&sh2[ci0 * 128], sw, tt, cb, CC, acc);
        }
        if (active) {
            #pragma unroll
            for (int p = 0; p < 5; p++) {
                int co = cb + 2 * p;
                float2 bv = *(const float2*)&b3[co];
                float4 v0 = { acc[p][0].x + bv.x, acc[p][1].x + bv.x,
                              acc[p][2].x + bv.x, acc[p][3].x + bv.x };
                float4 v1 = { acc[p][0].y + bv.y, acc[p][1].y + bv.y,
                              acc[p][2].y + bv.y, acc[p][3].y + bv.y };
                *(float4*)&y[((size_t)(b * 80) + co    ) * 800 + t0 + tt] = v0;
                *(float4*)&y[((size_t)(b * 80) + co + 1) * 800 + t0 + tt] = v1;
            }
        }
    }
}

__global__ void stageB_kernel(
    const float* __restrict__ k1in, const float* __restrict__ kb2, float* __restrict__ kout,
    const float* __restrict__ q1in, const float* __restrict__ qb2,
    const float* __restrict__ qb3, float* __restrict__ qout)
{
    extern __shared__ float smem[];
    int id = blockIdx.x;
    if (id < 32) key1x1_body(k1in, g_kw2T, kb2, kout, id >> 1, id & 1, smem);
    else {
        int j = id - 32;
        qchain_body(q1in, g_qw2T, qb2, g_qw3T, qb3, qout, j / 7, j % 7, smem);
    }
}

// =================== STAGE C: L2-dist + log_softmax + log(prior) ==========
// grid (50,16), block 256, t1 tile 16. smem 17.9KB -> 4-5 blocks/SM.
// k read straight from L2 (1MB, 25x reuse). ||k||^2, ||q||^2 fused into GEMM.
__global__ void attention_kernel(const float* __restrict__ q, const float* __restrict__ k,
                                 const float* __restrict__ prior, float* __restrict__ out)
{
    extern __shared__ float smem[];
    float* sq = smem;              // 80*16
    float* sd = smem + 1280;       // 16*200

    const int b    = blockIdx.y;
    const int t1_0 = blockIdx.x * 16;
    const int tid  = threadIdx.x;

    // stage q tile (float4 over the j dimension; t1_0 is 16-aligned)
    {
        int i = tid;               // 320 float4 loads
        if (i < 320) {
            int c = i >> 2, jq = (i & 3) << 2;
            *(float4*)&sq[c * 16 + jq] =
                *(const float4*)&q[((size_t)(b * 80) + c) * 800 + t1_0 + jq];
        }
        i = tid + 256;
        if (i < 320) {
            int c = i >> 2, jq = (i & 3) << 2;
            *(float4*)&sq[c * 16 + jq] =
                *(const float4*)&q[((size_t)(b * 80) + c) * 800 + t1_0 + jq];
        }
    }
    __syncthreads();

    // GEMM + fused norms: thread (sg<50, jg<4) -> 4 s x 4 j
    const int sg = tid & 63, jg = tid >> 6;
    if (sg < 50) {
        const int s0 = sg * 4, j0 = jg * 4;
        const float* kp = &k[(size_t)(b * 80) * 200 + s0];
        float2 acc[4][2] = {};      // [si][jpair]
        float2 k2p[2] = {}, q2p[2] = {};
        #pragma unroll 4
        for (int c = 0; c < 80; c++) {
            float4 kq = *(const float4*)(kp + c * 200);
            float4 qa = *(const float4*)&sq[c * 16 + j0];
            float2 qp[2] = { {qa.x, qa.y}, {qa.z, qa.w} };
            float2 kpair0 = { kq.x, kq.y }, kpair1 = { kq.z, kq.w };
            k2p[0] = ffma2(kpair0, kpair0, k2p[0]);
            k2p[1] = ffma2(kpair1, kpair1, k2p[1]);
            q2p[0] = ffma2(qp[0], qp[0], q2p[0]);
            q2p[1] = ffma2(qp[1], qp[1], q2p[1]);
            float ks[4] = { kq.x, kq.y, kq.z, kq.w };
            #pragma unroll
            for (int si = 0; si < 4; si++) {
                float2 kd = dup(ks[si]);
                acc[si][0] = ffma2(kd, qp[0], acc[si][0]);
                acc[si][1] = ffma2(kd, qp[1], acc[si][1]);
            }
        }
        float k2s[4] = { k2p[0].x, k2p[0].y, k2p[1].x, k2p[1].y };
        float q2s[4] = { q2p[0].x, q2p[0].y, q2p[1].x, q2p[1].y };
        #pragma unroll
        for (int jj = 0; jj < 4; jj++) {
            int p = jj >> 1;
            float a0 = (jj & 1) ? acc[0][p].y : acc[0][p].x;
            float a1 = (jj & 1) ? acc[1][p].y : acc[1][p].x;
            float a2 = (jj & 1) ? acc[2][p].y : acc[2][p].x;
            float a3 = (jj & 1) ? acc[3][p].y : acc[3][p].x;
            float4 v = { -0.0005f * (q2s[jj] + k2s[0] - 2.f * a0),
                         -0.0005f * (q2s[jj] + k2s[1] - 2.f * a1),
                         -0.0005f * (q2s[jj] + k2s[2] - 2.f * a2),
                         -0.0005f * (q2s[jj] + k2s[3] - 2.f * a3) };
            *(float4*)&sd[(j0 + jj) * 200 + s0] = v;
        }
    }
    __syncthreads();

    // epilogue: warp handles rows j = warp and warp+8; prior prefetched to regs
    const int warp = tid >> 5, lane = tid & 31;
    #pragma unroll
    for (int rr = 0; rr < 2; rr++) {
        int j = warp + rr * 8;
        const float* pr = &prior[((size_t)b * 800 + t1_0 + j) * 200];
        float prv[7];
        #pragma unroll
        for (int i = 0; i < 7; i++) {
            int s = lane + 32 * i;
            prv[i] = (s < 200) ? pr[s] : 1.f;
        }
        float m = -1e30f;
        #pragma unroll
        for (int i = 0; i < 7; i++) {
            int s = lane + 32 * i;
            if (s < 200) m = fmaxf(m, sd[j * 200 + s]);
        }
        #pragma unroll
        for (int o = 16; o; o >>= 1) m = fmaxf(m, __shfl_xor_sync(0xffffffffu, m, o));
        float sum = 0.f;
        #pragma unroll
        for (int i = 0; i < 7; i++) {
            int s = lane + 32 * i;
            if (s < 200) sum += __expf(sd[j * 200 + s] - m);
        }
        #pragma unroll
        for (int o = 16; o; o >>= 1) sum += __shfl_xor_sync(0xffffffffu, sum, o);
        float lse = m + __logf(sum);
        float* op = &out[((size_t)b * 800 + t1_0 + j) * 200];
        #pragma unroll
        for (int i = 0; i < 7; i++) {
            int s = lane + 32 * i;
            if (s < 200) op[s] = sd[j * 200 + s] - lse + __logf(prv[i] + 1e-8f);
        }
    }
}

// -------------------------------- launch ---------------------------------
extern "C" void kernel_launch(void* const* d_in, const int* in_sizes, int n_in,
                              void* d_out, int out_size)
{
    const float* queries = (const float*)d_in[0];
    const float* keys    = (const float*)d_in[1];
    const float* prior   = (const float*)d_in[2];
    const float* kw1 = (const float*)d_in[3];
    const float* kb1 = (const float*)d_in[4];
    const float* kw2 = (const float*)d_in[5];
    const float* kb2 = (const float*)d_in[6];
    const float* qw1 = (const float*)d_in[7];
    const float* qb1 = (const float*)d_in[8];
    const float* qw2 = (const float*)d_in[9];
    const float* qb2 = (const float*)d_in[10];
    const float* qw3 = (const float*)d_in[11];
    const float* qb3 = (const float*)d_in[12];
    float* out = (float*)d_out;

    float *k1buf, *kbuf, *q1buf, *qbuf;
    float *kw1T, *qw1T, *kw2T, *qw2T, *qw3T;
    cudaGetSymbolAddress((void**)&k1buf, g_k1);
    cudaGetSymbolAddress((void**)&kbuf,  g_k);
    cudaGetSymbolAddress((void**)&q1buf, g_q1);
    cudaGetSymbolAddress((void**)&qbuf,  g_qf);
    cudaGetSymbolAddress((void**)&kw1T, g_kw1T);
    cudaGetSymbolAddress((void**)&qw1T, g_qw1T);
    cudaGetSymbolAddress((void**)&kw2T, g_kw2T);
    cudaGetSymbolAddress((void**)&qw2T, g_qw2T);
    cudaGetSymbolAddress((void**)&qw3T, g_qw3T);

    const int smem_A    = (32 * 68 + 32 * 3 * 160) * 4;          // 70144
    const int smem_B    = (4096 + 2560 + 80 * 128) * 4;          // 67584
    const int smem_attn = (1280 + 16 * 200) * 4;                 // 17920

    cudaFuncSetAttribute((const void*)stageA_kernel,
                         cudaFuncAttributeMaxDynamicSharedMemorySize, smem_A);
    cudaFuncSetAttribute((const void*)stageB_kernel,
                         cudaFuncAttributeMaxDynamicSharedMemorySize, smem_B);

    prep_kernel<<<1921, 256>>>(kw1, qw1, kw2, qw2, qw3, kw1T, qw1T, kw2T, qw2T, qw3T);
    stageA_kernel<<<464, 256, smem_A>>>(keys, kb1, queries, qb1, k1buf, q1buf);
    stageB_kernel<<<144, 256, smem_B>>>(k1buf, kb2, kbuf, q1buf, qb2, qb3, qbuf);
    attention_kernel<<<dim3(50, 16), 256, smem_attn>>>(qbuf, kbuf, prior, out);
}

// round 8
// speedup vs baseline: 1.6405x; 1.0697x over previous
#include <cuda_runtime.h>
#include <math.h>

// ---------------- scratch (device globals; no allocation) ----------------
__device__ float g_k1  [16 * 512 * 200];   // key conv1 out
__device__ float g_k   [16 *  80 * 200];   // key encoder out
__device__ float g_q1  [16 * 160 * 800];   // query conv1 out
__device__ float g_qf  [16 *  80 * 800];   // query encoder out
__device__ float g_kw1T[768 * 512];        // kw1 transposed [(ci*3+k)][co]
__device__ float g_qw1T[240 * 160];
__device__ float g_kw2T[512 *  80];        // kw2 transposed [ci][co]
__device__ float g_qw2T[160 *  80];
__device__ float g_qw3T[ 80 *  80];

// ---------------- packed fp32x2 FMA (Blackwell) ---------------------------
__device__ __forceinline__ float2 ffma2(float2 a, float2 b, float2 c) {
    unsigned long long ua = *reinterpret_cast<unsigned long long*>(&a);
    unsigned long long ub = *reinterpret_cast<unsigned long long*>(&b);
    unsigned long long uc = *reinterpret_cast<unsigned long long*>(&c);
    unsigned long long ud;
    asm("fma.rn.f32x2 %0, %1, %2, %3;" : "=l"(ud) : "l"(ua), "l"(ub), "l"(uc));
    return *reinterpret_cast<float2*>(&ud);
}
__device__ __forceinline__ float2 dup(float v) { return make_float2(v, v); }

// =================== PREP: transpose all weights ==========================
__global__ void prep_kernel(const float* __restrict__ kw1, const float* __restrict__ qw1,
                            const float* __restrict__ kw2, const float* __restrict__ qw2,
                            const float* __restrict__ qw3,
                            float* __restrict__ kw1T, float* __restrict__ qw1T,
                            float* __restrict__ kw2T, float* __restrict__ qw2T,
                            float* __restrict__ qw3T)
{
    int i = blockIdx.x * 256 + threadIdx.x;
    if (i < 393216) {                    // kw1: (512,256,3)
        int r = i >> 9, co = i & 511;
        int ci = r / 3, k = r - ci * 3;
        kw1T[i] = kw1[(co * 256 + ci) * 3 + k];
        return;
    }
    i -= 393216;
    if (i < 38400) {                     // qw1: (160,80,3)
        int r = i / 160, co = i - r * 160;
        int ci = r / 3, k = r - ci * 3;
        qw1T[i] = qw1[(co * 80 + ci) * 3 + k];
        return;
    }
    i -= 38400;
    if (i < 40960) {                     // kw2: (80,512,1)
        int ci = i / 80, co = i - ci * 80;
        kw2T[i] = kw2[co * 512 + ci];
        return;
    }
    i -= 40960;
    if (i < 12800) {                     // qw2: (80,160,1)
        int ci = i / 80, co = i - ci * 80;
        qw2T[i] = qw2[co * 160 + ci];
        return;
    }
    i -= 12800;
    if (i < 6400) {                      // qw3: (80,80,1)
        int ci = i / 80, co = i - ci * 80;
        qw3T[i] = qw3[co * 80 + ci];
    }
}

// =================== STAGE A: both k=3 pad=1 convs (unchanged) ============
template<int CIN, int COUT, int TLEN, int CPAIRS>
__device__ __forceinline__ void conv3_body(
    const float* __restrict__ x, const float* __restrict__ wT,
    const float* __restrict__ bias, float* __restrict__ y,
    int b, int t_tile, int co_tile, float* smem)
{
    constexpr int COT = 32 * CPAIRS;
    float* sx = smem;               // 32*68
    float* sw = smem + 32 * 68;     // 32*3*COT

    const int tid = threadIdx.x;
    const int cg = tid & 15, tg = tid >> 4;
    const int tt = tg * 4, ct = cg * 2 * CPAIRS;
    const int t0 = t_tile * 64, co0 = co_tile * COT;
    const bool active = (t0 + tt) < TLEN;

    float2 acc[CPAIRS][4] = {};

    for (int ci0 = 0; ci0 < CIN; ci0 += 32) {
        const int CC = (CIN - ci0 < 32) ? (CIN - ci0) : 32;
        __syncthreads();
        for (int idx = tid; idx < CC * 66; idx += 256) {
            int cc = idx / 66, j = idx - cc * 66;
            int t = t0 + j - 1;
            sx[cc * 68 + j] = (t >= 0 && t < TLEN)
                ? x[((size_t)(b * CIN) + ci0 + cc) * TLEN + t] : 0.f;
        }
        for (int idx = tid; idx < CC * 3 * COT; idx += 256) {
            int r = idx / COT, co = idx - r * COT;
            sw[idx] = wT[(size_t)(ci0 * 3 + r) * COUT + co0 + co];
        }
        __syncthreads();
        if (active) {
            #pragma unroll 8
            for (int cc = 0; cc < CC; cc++) {
                const float* xr = &sx[cc * 68 + tt];
                float4 xa = *(const float4*)xr;
                float2 xb = *(const float2*)(xr + 4);
                float2 xv[6] = { dup(xa.x), dup(xa.y), dup(xa.z),
                                 dup(xa.w), dup(xb.x), dup(xb.y) };
                float2 wk[3][CPAIRS];
                #pragma unroll
                for (int k = 0; k < 3; k++) {
                    const float* wb = &sw[(cc * 3 + k) * COT + ct];
                    if constexpr ((CPAIRS & 1) == 0) {
                        #pragma unroll
                        for (int q = 0; q < CPAIRS / 2; q++) {
                            float4 wv = *(const float4*)(wb + 4 * q);
                            wk[k][2*q]   = make_float2(wv.x, wv.y);
                            wk[k][2*q+1] = make_float2(wv.z, wv.w);
                        }
                    } else {
                        #pragma unroll
                        for (int p = 0; p < CPAIRS; p++)
                            wk[k][p] = *(const float2*)(wb + 2 * p);
                    }
                }
                #pragma unroll
                for (int u = 0; u < 4; u++)
                    #pragma unroll
                    for (int p = 0; p < CPAIRS; p++)
                        acc[p][u] = ffma2(wk[0][p], xv[u],
                                    ffma2(wk[1][p], xv[u+1],
                                    ffma2(wk[2][p], xv[u+2], acc[p][u])));
            }
        }
    }

    if (active) {
        #pragma unroll
        for (int p = 0; p < CPAIRS; p++) {
            int co = co0 + ct + 2 * p;
            float2 bv = *(const float2*)&bias[co];
            float4 v0 = { fmaxf(acc[p][0].x + bv.x, 0.f), fmaxf(acc[p][1].x + bv.x, 0.f),
                          fmaxf(acc[p][2].x + bv.x, 0.f), fmaxf(acc[p][3].x + bv.x, 0.f) };
            float4 v1 = { fmaxf(acc[p][0].y + bv.y, 0.f), fmaxf(acc[p][1].y + bv.y, 0.f),
                          fmaxf(acc[p][2].y + bv.y, 0.f), fmaxf(acc[p][3].y + bv.y, 0.f) };
            *(float4*)&y[((size_t)(b * COUT) + co    ) * TLEN + t0 + tt] = v0;
            *(float4*)&y[((size_t)(b * COUT) + co + 1) * TLEN + t0 + tt] = v1;
        }
    }
}

__global__ void stageA_kernel(
    const float* __restrict__ keys, const float* __restrict__ kb1,
    const float* __restrict__ queries, const float* __restrict__ qb1,
    float* __restrict__ k1out, float* __restrict__ q1out)
{
    extern __shared__ float smem[];
    int id = blockIdx.x;
    if (id < 256) {
        int r = id & 15;
        conv3_body<256, 512, 200, 4>(keys, g_kw1T, kb1, k1out,
                                     id >> 4, r & 3, r >> 2, smem);
    } else {
        int j = id - 256;
        conv3_body<80, 160, 800, 5>(queries, g_qw1T, qb1, q1out,
                                    j / 13, j % 13, 0, smem);
    }
}

// =================== STAGE B: key 1x1 (t-split) + query 1x1 chain =========
__device__ __forceinline__ void fma1x1_chunk(
    const float* __restrict__ sx, const float* __restrict__ sw,
    int tt, int cb, int CC, float2 acc[5][4])
{
    #pragma unroll 8
    for (int cc = 0; cc < CC; cc++) {
        float4 xq = *(const float4*)&sx[cc * 128 + tt];
        float2 xv[4] = { dup(xq.x), dup(xq.y), dup(xq.z), dup(xq.w) };
        const float2* wp = (const float2*)&sw[cc * 80 + cb];
        #pragma unroll
        for (int p = 0; p < 5; p++) {
            float2 wd = wp[p];
            #pragma unroll
            for (int u = 0; u < 4; u++)
                acc[p][u] = ffma2(wd, xv[u], acc[p][u]);
        }
    }
}

// key 1x1: t-tile 64, 64 blocks (4 per batch). 256 thr = 8 cg x 32 tg, 10co x 2t.
__device__ __forceinline__ void key1x1_body(
    const float* __restrict__ x, const float* __restrict__ wT,
    const float* __restrict__ bias, float* __restrict__ y,
    int b, int t_tile, float* smem)
{
    float* sx = smem;          // 32*64
    float* sw = smem + 4096;   // 32*80
    const int tid = threadIdx.x;
    const int cg = tid & 7, tg = tid >> 3;
    const int tt = tg * 2, cb = cg * 10;
    const int t0 = t_tile * 64;
    const bool active = (t0 + tt) < 200;
    float2 acc[5][2] = {};

    for (int ci0 = 0; ci0 < 512; ci0 += 32) {
        __syncthreads();
        for (int idx = tid; idx < 2048; idx += 256) {
            int cc = idx >> 6, j = idx & 63;
            int t = t0 + j;
            sx[idx] = (t < 200) ? x[((size_t)(b * 512) + ci0 + cc) * 200 + t] : 0.f;
        }
        for (int idx = tid; idx < 2560; idx += 256)
            sw[idx] = wT[(size_t)ci0 * 80 + idx];
        __syncthreads();
        if (active) {
            #pragma unroll 8
            for (int cc = 0; cc < 32; cc++) {
                float2 xq = *(const float2*)&sx[cc * 64 + tt];
                float2 x0 = dup(xq.x), x1 = dup(xq.y);
                const float2* wp = (const float2*)&sw[cc * 80 + cb];
                #pragma unroll
                for (int p = 0; p < 5; p++) {
                    float2 wd = wp[p];
                    acc[p][0] = ffma2(wd, x0, acc[p][0]);
                    acc[p][1] = ffma2(wd, x1, acc[p][1]);
                }
            }
        }
    }
    if (active) {
        #pragma unroll
        for (int p = 0; p < 5; p++) {
            int co = cb + 2 * p;
            float2 bv = *(const float2*)&bias[co];
            float2 v0 = { acc[p][0].x + bv.x, acc[p][1].x + bv.x };
            float2 v1 = { acc[p][0].y + bv.y, acc[p][1].y + bv.y };
            *(float2*)&y[((size_t)(b * 80) + co    ) * 200 + t0 + tt] = v0;
            *(float2*)&y[((size_t)(b * 80) + co + 1) * 200 + t0 + tt] = v1;
        }
    }
}

__device__ __forceinline__ void qchain_body(
    const float* __restrict__ x, const float* __restrict__ w2T, const float* __restrict__ b2,
    const float* __restrict__ w3T, const float* __restrict__ b3,
    float* __restrict__ y, int b, int t_tile, float* smem)
{
    float* sx  = smem;          // 32*128
    float* sw  = smem + 4096;   // 32*80
    float* sh2 = smem + 6656;   // 80*128
    const int tid = threadIdx.x;
    const int cg = tid & 7, tg = tid >> 3;
    const int tt = tg * 4, cb = cg * 10;
    const int t0 = t_tile * 128;
    const bool active = (t0 + tt) < 800;

    {   // phase 1: h2 = relu(W2 x + b2), CIN=160 -> sh2
        float2 acc[5][4] = {};
        for (int ci0 = 0; ci0 < 160; ci0 += 32) {
            __syncthreads();
            for (int idx = tid; idx < 4096; idx += 256) {
                int cc = idx >> 7, j = idx & 127;
                int t = t0 + j;
                sx[idx] = (t < 800) ? x[((size_t)(b * 160) + ci0 + cc) * 800 + t] : 0.f;
            }
            for (int idx = tid; idx < 2560; idx += 256)
                sw[idx] = w2T[(size_t)ci0 * 80 + idx];
            __syncthreads();
            if (active) fma1x1_chunk(sx, sw, tt, cb, 32, acc);
        }
        if (active) {
            #pragma unroll
            for (int p = 0; p < 5; p++) {
                int co = cb + 2 * p;
                float2 bv = *(const float2*)&b2[co];
                float4 v0 = { fmaxf(acc[p][0].x + bv.x, 0.f), fmaxf(acc[p][1].x + bv.x, 0.f),
                              fmaxf(acc[p][2].x + bv.x, 0.f), fmaxf(acc[p][3].x + bv.x, 0.f) };
                float4 v1 = { fmaxf(acc[p][0].y + bv.y, 0.f), fmaxf(acc[p][1].y + bv.y, 0.f),
                              fmaxf(acc[p][2].y + bv.y, 0.f), fmaxf(acc[p][3].y + bv.y, 0.f) };
                *(float4*)&sh2[(co    ) * 128 + tt] = v0;
                *(float4*)&sh2[(co + 1) * 128 + tt] = v1;
            }
        }
    }
    {   // phase 2: q = W3 h2 + b3, CIN=80 (h2 in smem)
        float2 acc[5][4] = {};
        for (int ci0 = 0; ci0 < 80; ci0 += 32) {
            const int CC = (80 - ci0 < 32) ? (80 - ci0) : 32;
            __syncthreads();
            for (int idx = tid; idx < CC * 80; idx += 256)
                sw[idx] = w3T[(size_t)ci0 * 80 + idx];
            __syncthreads();
            if (active) fma1x1_chunk(&sh2[ci0 * 128], sw, tt, cb, CC, acc);
        }
        if (active) {
            #pragma unroll
            for (int p = 0; p < 5; p++) {
                int co = cb + 2 * p;
                float2 bv = *(const float2*)&b3[co];
                float4 v0 = { acc[p][0].x + bv.x, acc[p][1].x + bv.x,
                              acc[p][2].x + bv.x, acc[p][3].x + bv.x };
                float4 v1 = { acc[p][0].y + bv.y, acc[p][1].y + bv.y,
                              acc[p][2].y + bv.y, acc[p][3].y + bv.y };
                *(float4*)&y[((size_t)(b * 80) + co    ) * 800 + t0 + tt] = v0;
                *(float4*)&y[((size_t)(b * 80) + co + 1) * 800 + t0 + tt] = v1;
            }
        }
    }
}

__global__ void stageB_kernel(
    const float* __restrict__ k1in, const float* __restrict__ kb2, float* __restrict__ kout,
    const float* __restrict__ q1in, const float* __restrict__ qb2,
    const float* __restrict__ qb3, float* __restrict__ qout)
{
    extern __shared__ float smem[];
    int id = blockIdx.x;
    if (id < 64) key1x1_body(k1in, g_kw2T, kb2, kout, id >> 2, id & 3, smem);
    else {
        int j = id - 64;
        qchain_body(q1in, g_qw2T, qb2, g_qw3T, qb3, qout, j / 7, j % 7, smem);
    }
}

// =================== STAGE C: L2-dist + log_softmax + log(prior) ==========
// grid (50,16), block 256, t1 tile 16. k loads software-pipelined (chunks of 4).
__global__ void attention_kernel(const float* __restrict__ q, const float* __restrict__ k,
                                 const float* __restrict__ prior, float* __restrict__ out)
{
    extern __shared__ float smem[];
    float* sq = smem;              // 80*16
    float* sd = smem + 1280;       // 16*200

    const int b    = blockIdx.y;
    const int t1_0 = blockIdx.x * 16;
    const int tid  = threadIdx.x;

    {
        int i = tid;
        if (i < 320) {
            int c = i >> 2, jq = (i & 3) << 2;
            *(float4*)&sq[c * 16 + jq] =
                *(const float4*)&q[((size_t)(b * 80) + c) * 800 + t1_0 + jq];
        }
        i = tid + 256;
        if (i < 320) {
            int c = i >> 2, jq = (i & 3) << 2;
            *(float4*)&sq[c * 16 + jq] =
                *(const float4*)&q[((size_t)(b * 80) + c) * 800 + t1_0 + jq];
        }
    }
    __syncthreads();

    const int sg = tid & 63, jg = tid >> 6;
    if (sg < 50) {
        const int s0 = sg * 4, j0 = jg * 4;
        const float* kp = &k[(size_t)(b * 80) * 200 + s0];
        float2 acc[4][2] = {};
        float2 k2p[2] = {}, q2p[2] = {};

        float4 kbuf[4];
        #pragma unroll
        for (int i = 0; i < 4; i++) kbuf[i] = *(const float4*)(kp + i * 200);

        #pragma unroll
        for (int c0 = 0; c0 < 80; c0 += 4) {
            float4 cur[4];
            #pragma unroll
            for (int i = 0; i < 4; i++) cur[i] = kbuf[i];
            if (c0 + 4 < 80) {
                #pragma unroll
                for (int i = 0; i < 4; i++)
                    kbuf[i] = *(const float4*)(kp + (c0 + 4 + i) * 200);
            }
            #pragma unroll
            for (int i = 0; i < 4; i++) {
                int c = c0 + i;
                float4 kq = cur[i];
                float4 qa = *(const float4*)&sq[c * 16 + j0];
                float2 qp[2] = { {qa.x, qa.y}, {qa.z, qa.w} };
                float2 kpair0 = { kq.x, kq.y }, kpair1 = { kq.z, kq.w };
                k2p[0] = ffma2(kpair0, kpair0, k2p[0]);
                k2p[1] = ffma2(kpair1, kpair1, k2p[1]);
                q2p[0] = ffma2(qp[0], qp[0], q2p[0]);
                q2p[1] = ffma2(qp[1], qp[1], q2p[1]);
                float ks[4] = { kq.x, kq.y, kq.z, kq.w };
                #pragma unroll
                for (int si = 0; si < 4; si++) {
                    float2 kd = dup(ks[si]);
                    acc[si][0] = ffma2(kd, qp[0], acc[si][0]);
                    acc[si][1] = ffma2(kd, qp[1], acc[si][1]);
                }
            }
        }
        float k2s[4] = { k2p[0].x, k2p[0].y, k2p[1].x, k2p[1].y };
        float q2s[4] = { q2p[0].x, q2p[0].y, q2p[1].x, q2p[1].y };
        #pragma unroll
        for (int jj = 0; jj < 4; jj++) {
            int p = jj >> 1;
            float a0 = (jj & 1) ? acc[0][p].y : acc[0][p].x;
            float a1 = (jj & 1) ? acc[1][p].y : acc[1][p].x;
            float a2 = (jj & 1) ? acc[2][p].y : acc[2][p].x;
            float a3 = (jj & 1) ? acc[3][p].y : acc[3][p].x;
            float4 v = { -0.0005f * (q2s[jj] + k2s[0] - 2.f * a0),
                         -0.0005f * (q2s[jj] + k2s[1] - 2.f * a1),
                         -0.0005f * (q2s[jj] + k2s[2] - 2.f * a2),
                         -0.0005f * (q2s[jj] + k2s[3] - 2.f * a3) };
            *(float4*)&sd[(j0 + jj) * 200 + s0] = v;
        }
    }
    __syncthreads();

    const int warp = tid >> 5, lane = tid & 31;
    #pragma unroll
    for (int rr = 0; rr < 2; rr++) {
        int j = warp + rr * 8;
        const float* pr = &prior[((size_t)b * 800 + t1_0 + j) * 200];
        float prv[7];
        #pragma unroll
        for (int i = 0; i < 7; i++) {
            int s = lane + 32 * i;
            prv[i] = (s < 200) ? pr[s] : 1.f;
        }
        float m = -1e30f;
        #pragma unroll
        for (int i = 0; i < 7; i++) {
            int s = lane + 32 * i;
            if (s < 200) m = fmaxf(m, sd[j * 200 + s]);
        }
        #pragma unroll
        for (int o = 16; o; o >>= 1) m = fmaxf(m, __shfl_xor_sync(0xffffffffu, m, o));
        float sum = 0.f;
        #pragma unroll
        for (int i = 0; i < 7; i++) {
            int s = lane + 32 * i;
            if (s < 200) sum += __expf(sd[j * 200 + s] - m);
        }
        #pragma unroll
        for (int o = 16; o; o >>= 1) sum += __shfl_xor_sync(0xffffffffu, sum, o);
        float lse = m + __logf(sum);
        float* op = &out[((size_t)b * 800 + t1_0 + j) * 200];
        #pragma unroll
        for (int i = 0; i < 7; i++) {
            int s = lane + 32 * i;
            if (s < 200) op[s] = sd[j * 200 + s] - lse + __logf(prv[i] + 1e-8f);
        }
    }
}

// -------------------------------- launch ---------------------------------
extern "C" void kernel_launch(void* const* d_in, const int* in_sizes, int n_in,
                              void* d_out, int out_size)
{
    const float* queries = (const float*)d_in[0];
    const float* keys    = (const float*)d_in[1];
    const float* prior   = (const float*)d_in[2];
    const float* kw1 = (const float*)d_in[3];
    const float* kb1 = (const float*)d_in[4];
    const float* kw2 = (const float*)d_in[5];
    const float* kb2 = (const float*)d_in[6];
    const float* qw1 = (const float*)d_in[7];
    const float* qb1 = (const float*)d_in[8];
    const float* qw2 = (const float*)d_in[9];
    const float* qb2 = (const float*)d_in[10];
    const float* qw3 = (const float*)d_in[11];
    const float* qb3 = (const float*)d_in[12];
    float* out = (float*)d_out;

    float *k1buf, *kbuf, *q1buf, *qbuf;
    float *kw1T, *qw1T, *kw2T, *qw2T, *qw3T;
    cudaGetSymbolAddress((void**)&k1buf, g_k1);
    cudaGetSymbolAddress((void**)&kbuf,  g_k);
    cudaGetSymbolAddress((void**)&q1buf, g_q1);
    cudaGetSymbolAddress((void**)&qbuf,  g_qf);
    cudaGetSymbolAddress((void**)&kw1T, g_kw1T);
    cudaGetSymbolAddress((void**)&qw1T, g_qw1T);
    cudaGetSymbolAddress((void**)&kw2T, g_kw2T);
    cudaGetSymbolAddress((void**)&qw2T, g_qw2T);
    cudaGetSymbolAddress((void**)&qw3T, g_qw3T);

    const int smem_A    = (32 * 68 + 32 * 3 * 160) * 4;          // 70144
    const int smem_B    = (4096 + 2560 + 80 * 128) * 4;          // 67584
    const int smem_attn = (1280 + 16 * 200) * 4;                 // 17920

    cudaFuncSetAttribute((const void*)stageA_kernel,
                         cudaFuncAttributeMaxDynamicSharedMemorySize, smem_A);
    cudaFuncSetAttribute((const void*)stageB_kernel,
                         cudaFuncAttributeMaxDynamicSharedMemorySize, smem_B);

    prep_kernel<<<1921, 256>>>(kw1, qw1, kw2, qw2, qw3, kw1T, qw1T, kw2T, qw2T, qw3T);
    stageA_kernel<<<464, 256, smem_A>>>(keys, kb1, queries, qb1, k1buf, q1buf);
    stageB_kernel<<<176, 256, smem_B>>>(k1buf, kb2, kbuf, q1buf, qb2, qb3, qbuf);
    attention_kernel<<<dim3(50, 16), 256, smem_attn>>>(qbuf, kbuf, prior, out);
}

// round 9
// speedup vs baseline: 1.7305x; 1.0549x over previous
#include <cuda_runtime.h>
#include <math.h>

// ---------------- scratch (device globals; no allocation) ----------------
__device__ float g_k1  [16 * 512 * 200];   // key conv1 out
__device__ float g_k   [16 *  80 * 200];   // key encoder out
__device__ float g_q1  [16 * 160 * 800];   // query conv1 out
__device__ float g_qf  [16 *  80 * 800];   // query encoder out
__device__ float g_kw1T[768 * 512];        // kw1 transposed [(ci*3+k)][co]
__device__ float g_qw1T[240 * 160];
__device__ float g_kw2T[512 *  80];        // kw2 transposed [ci][co]
__device__ float g_qw2T[160 *  80];
__device__ float g_qw3T[ 80 *  80];

// ---------------- packed fp32x2 FMA (Blackwell) ---------------------------
__device__ __forceinline__ float2 ffma2(float2 a, float2 b, float2 c) {
    unsigned long long ua = *reinterpret_cast<unsigned long long*>(&a);
    unsigned long long ub = *reinterpret_cast<unsigned long long*>(&b);
    unsigned long long uc = *reinterpret_cast<unsigned long long*>(&c);
    unsigned long long ud;
    asm("fma.rn.f32x2 %0, %1, %2, %3;" : "=l"(ud) : "l"(ua), "l"(ub), "l"(uc));
    return *reinterpret_cast<float2*>(&ud);
}
__device__ __forceinline__ float2 dup(float v) { return make_float2(v, v); }

// =================== PREP: transpose all weights ==========================
__global__ void prep_kernel(const float* __restrict__ kw1, const float* __restrict__ qw1,
                            const float* __restrict__ kw2, const float* __restrict__ qw2,
                            const float* __restrict__ qw3,
                            float* __restrict__ kw1T, float* __restrict__ qw1T,
                            float* __restrict__ kw2T, float* __restrict__ qw2T,
                            float* __restrict__ qw3T)
{
    int i = blockIdx.x * 256 + threadIdx.x;
    if (i < 393216) {                    // kw1: (512,256,3)
        int r = i >> 9, co = i & 511;
        int ci = r / 3, k = r - ci * 3;
        kw1T[i] = kw1[(co * 256 + ci) * 3 + k];
        return;
    }
    i -= 393216;
    if (i < 38400) {                     // qw1: (160,80,3)
        int r = i / 160, co = i - r * 160;
        int ci = r / 3, k = r - ci * 3;
        qw1T[i] = qw1[(co * 80 + ci) * 3 + k];
        return;
    }
    i -= 38400;
    if (i < 40960) {                     // kw2: (80,512,1)
        int ci = i / 80, co = i - ci * 80;
        kw2T[i] = kw2[co * 512 + ci];
        return;
    }
    i -= 40960;
    if (i < 12800) {                     // qw2: (80,160,1)
        int ci = i / 80, co = i - ci * 80;
        qw2T[i] = qw2[co * 160 + ci];
        return;
    }
    i -= 12800;
    if (i < 6400) {                      // qw3: (80,80,1)
        int ci = i / 80, co = i - ci * 80;
        qw3T[i] = qw3[co * 80 + ci];
    }
}

// =================== STAGE A: both k=3 pad=1 convs ========================
// 256 threads = 16 cg x 16 tg; thread tile = (2*CPAIRS) co x 4 t (co-paired f32x2).
// block tile = 32*CPAIRS co x 64 t.  ci chunks of CICH (16) -> small smem.
// smem: sx[CICH][68] + sw[CICH*3][COT]
template<int CIN, int COUT, int TLEN, int CPAIRS, int CICH>
__device__ __forceinline__ void conv3_body(
    const float* __restrict__ x, const float* __restrict__ wT,
    const float* __restrict__ bias, float* __restrict__ y,
    int b, int t_tile, int co_tile, float* smem)
{
    constexpr int COT = 32 * CPAIRS;
    constexpr int NW4 = CICH * 3 * COT / 4;     // float4 weight loads per chunk
    float* sx = smem;                   // CICH * 68
    float* sw = smem + CICH * 68;       // CICH*3*COT

    const int tid = threadIdx.x;
    const int cg = tid & 15, tg = tid >> 4;
    const int tt = tg * 4, ct = cg * 2 * CPAIRS;
    const int t0 = t_tile * 64, co0 = co_tile * COT;
    const bool active = (t0 + tt) < TLEN;

    float2 acc[CPAIRS][4] = {};

    for (int ci0 = 0; ci0 < CIN; ci0 += CICH) {
        __syncthreads();
        for (int idx = tid; idx < CICH * 66; idx += 256) {
            int cc = idx / 66, j = idx - cc * 66;
            int t = t0 + j - 1;
            sx[cc * 68 + j] = (t >= 0 && t < TLEN)
                ? x[((size_t)(b * CIN) + ci0 + cc) * TLEN + t] : 0.f;
        }
        // vectorized weight staging (wT rows contiguous in co)
        for (int idx = tid; idx < NW4; idx += 256) {
            int r = idx / (COT / 4), c4 = idx - r * (COT / 4);
            ((float4*)sw)[idx] =
                *(const float4*)&wT[(size_t)(ci0 * 3 + r) * COUT + co0 + c4 * 4];
        }
        __syncthreads();
        if (active) {
            #pragma unroll
            for (int cc = 0; cc < CICH; cc++) {
                const float* xr = &sx[cc * 68 + tt];
                float4 xa = *(const float4*)xr;
                float2 xb = *(const float2*)(xr + 4);
                float2 xv[6] = { dup(xa.x), dup(xa.y), dup(xa.z),
                                 dup(xa.w), dup(xb.x), dup(xb.y) };
                float2 wk[3][CPAIRS];
                #pragma unroll
                for (int k = 0; k < 3; k++) {
                    const float* wb = &sw[(cc * 3 + k) * COT + ct];
                    if constexpr ((CPAIRS & 1) == 0) {
                        #pragma unroll
                        for (int q = 0; q < CPAIRS / 2; q++) {
                            float4 wv = *(const float4*)(wb + 4 * q);
                            wk[k][2*q]   = make_float2(wv.x, wv.y);
                            wk[k][2*q+1] = make_float2(wv.z, wv.w);
                        }
                    } else {
                        #pragma unroll
                        for (int p = 0; p < CPAIRS; p++)
                            wk[k][p] = *(const float2*)(wb + 2 * p);
                    }
                }
                #pragma unroll
                for (int u = 0; u < 4; u++)
                    #pragma unroll
                    for (int p = 0; p < CPAIRS; p++)
                        acc[p][u] = ffma2(wk[0][p], xv[u],
                                    ffma2(wk[1][p], xv[u+1],
                                    ffma2(wk[2][p], xv[u+2], acc[p][u])));
            }
        }
    }

    if (active) {
        #pragma unroll
        for (int p = 0; p < CPAIRS; p++) {
            int co = co0 + ct + 2 * p;
            float2 bv = *(const float2*)&bias[co];
            float4 v0 = { fmaxf(acc[p][0].x + bv.x, 0.f), fmaxf(acc[p][1].x + bv.x, 0.f),
                          fmaxf(acc[p][2].x + bv.x, 0.f), fmaxf(acc[p][3].x + bv.x, 0.f) };
            float4 v1 = { fmaxf(acc[p][0].y + bv.y, 0.f), fmaxf(acc[p][1].y + bv.y, 0.f),
                          fmaxf(acc[p][2].y + bv.y, 0.f), fmaxf(acc[p][3].y + bv.y, 0.f) };
            *(float4*)&y[((size_t)(b * COUT) + co    ) * TLEN + t0 + tt] = v0;
            *(float4*)&y[((size_t)(b * COUT) + co + 1) * TLEN + t0 + tt] = v1;
        }
    }
}

__global__ void __launch_bounds__(256)
stageA_kernel(
    const float* __restrict__ keys, const float* __restrict__ kb1,
    const float* __restrict__ queries, const float* __restrict__ qb1,
    float* __restrict__ k1out, float* __restrict__ q1out)
{
    extern __shared__ float smem[];
    int id = blockIdx.x;
    if (id < 512) {                      // key: 8 co-tiles x 4 t-tiles x 16 b
        int b = id >> 5, r = id & 31;
        conv3_body<256, 512, 200, 2, 16>(keys, g_kw1T, kb1, k1out,
                                         b, r & 3, r >> 2, smem);
    } else {                             // query: 13 t-tiles x 16 b, full 160 co
        int j = id - 512;
        conv3_body<80, 160, 800, 5, 16>(queries, g_qw1T, qb1, q1out,
                                        j / 13, j % 13, 0, smem);
    }
}

// =================== STAGE B: key 1x1 (t-split) + query 1x1 chain =========
__device__ __forceinline__ void fma1x1_chunk(
    const float* __restrict__ sx, const float* __restrict__ sw,
    int tt, int cb, int CC, float2 acc[5][4])
{
    #pragma unroll 8
    for (int cc = 0; cc < CC; cc++) {
        float4 xq = *(const float4*)&sx[cc * 128 + tt];
        float2 xv[4] = { dup(xq.x), dup(xq.y), dup(xq.z), dup(xq.w) };
        const float2* wp = (const float2*)&sw[cc * 80 + cb];
        #pragma unroll
        for (int p = 0; p < 5; p++) {
            float2 wd = wp[p];
            #pragma unroll
            for (int u = 0; u < 4; u++)
                acc[p][u] = ffma2(wd, xv[u], acc[p][u]);
        }
    }
}

// key 1x1: t-tile 64, 64 blocks (4 per batch). 256 thr = 8 cg x 32 tg, 10co x 2t.
__device__ __forceinline__ void key1x1_body(
    const float* __restrict__ x, const float* __restrict__ wT,
    const float* __restrict__ bias, float* __restrict__ y,
    int b, int t_tile, float* smem)
{
    float* sx = smem;          // 32*64
    float* sw = smem + 4096;   // 32*80
    const int tid = threadIdx.x;
    const int cg = tid & 7, tg = tid >> 3;
    const int tt = tg * 2, cb = cg * 10;
    const int t0 = t_tile * 64;
    const bool active = (t0 + tt) < 200;
    float2 acc[5][2] = {};

    for (int ci0 = 0; ci0 < 512; ci0 += 32) {
        __syncthreads();
        for (int idx = tid; idx < 2048; idx += 256) {
            int cc = idx >> 6, j = idx & 63;
            int t = t0 + j;
            sx[idx] = (t < 200) ? x[((size_t)(b * 512) + ci0 + cc) * 200 + t] : 0.f;
        }
        for (int idx = tid; idx < 2560; idx += 256)
            sw[idx] = wT[(size_t)ci0 * 80 + idx];
        __syncthreads();
        if (active) {
            #pragma unroll 8
            for (int cc = 0; cc < 32; cc++) {
                float2 xq = *(const float2*)&sx[cc * 64 + tt];
                float2 x0 = dup(xq.x), x1 = dup(xq.y);
                const float2* wp = (const float2*)&sw[cc * 80 + cb];
                #pragma unroll
                for (int p = 0; p < 5; p++) {
                    float2 wd = wp[p];
                    acc[p][0] = ffma2(wd, x0, acc[p][0]);
                    acc[p][1] = ffma2(wd, x1, acc[p][1]);
                }
            }
        }
    }
    if (active) {
        #pragma unroll
        for (int p = 0; p < 5; p++) {
            int co = cb + 2 * p;
            float2 bv = *(const float2*)&bias[co];
            float2 v0 = { acc[p][0].x + bv.x, acc[p][1].x + bv.x };
            float2 v1 = { acc[p][0].y + bv.y, acc[p][1].y + bv.y };
            *(float2*)&y[((size_t)(b * 80) + co    ) * 200 + t0 + tt] = v0;
            *(float2*)&y[((size_t)(b * 80) + co + 1) * 200 + t0 + tt] = v1;
        }
    }
}

__device__ __forceinline__ void qchain_body(
    const float* __restrict__ x, const float* __restrict__ w2T, const float* __restrict__ b2,
    const float* __restrict__ w3T, const float* __restrict__ b3,
    float* __restrict__ y, int b, int t_tile, float* smem)
{
    float* sx  = smem;          // 32*128
    float* sw  = smem + 4096;   // 32*80
    float* sh2 = smem + 6656;   // 80*128
    const int tid = threadIdx.x;
    const int cg = tid & 7, tg = tid >> 3;
    const int tt = tg * 4, cb = cg * 10;
    const int t0 = t_tile * 128;
    const bool active = (t0 + tt) < 800;

    {   // phase 1: h2 = relu(W2 x + b2), CIN=160 -> sh2
        float2 acc[5][4] = {};
        for (int ci0 = 0; ci0 < 160; ci0 += 32) {
            __syncthreads();
            for (int idx = tid; idx < 4096; idx += 256) {
                int cc = idx >> 7, j = idx & 127;
                int t = t0 + j;
                sx[idx] = (t < 800) ? x[((size_t)(b * 160) + ci0 + cc) * 800 + t] : 0.f;
            }
            for (int idx = tid; idx < 2560; idx += 256)
                sw[idx] = w2T[(size_t)ci0 * 80 + idx];
            __syncthreads();
            if (active) fma1x1_chunk(sx, sw, tt, cb, 32, acc);
        }
        if (active) {
            #pragma unroll
            for (int p = 0; p < 5; p++) {
                int co = cb + 2 * p;
                float2 bv = *(const float2*)&b2[co];
                float4 v0 = { fmaxf(acc[p][0].x + bv.x, 0.f), fmaxf(acc[p][1].x + bv.x, 0.f),
                              fmaxf(acc[p][2].x + bv.x, 0.f), fmaxf(acc[p][3].x + bv.x, 0.f) };
                float4 v1 = { fmaxf(acc[p][0].y + bv.y, 0.f), fmaxf(acc[p][1].y + bv.y, 0.f),
                              fmaxf(acc[p][2].y + bv.y, 0.f), fmaxf(acc[p][3].y + bv.y, 0.f) };
                *(float4*)&sh2[(co    ) * 128 + tt] = v0;
                *(float4*)&sh2[(co + 1) * 128 + tt] = v1;
            }
        }
    }
    {   // phase 2: q = W3 h2 + b3, CIN=80 (h2 in smem)
        float2 acc[5][4] = {};
        for (int ci0 = 0; ci0 < 80; ci0 += 32) {
            const int CC = (80 - ci0 < 32) ? (80 - ci0) : 32;
            __syncthreads();
            for (int idx = tid; idx < CC * 80; idx += 256)
                sw[idx] = w3T[(size_t)ci0 * 80 + idx];
            __syncthreads();
            if (active) fma1x1_chunk(&sh2[ci0 * 128], sw, tt, cb, CC, acc);
        }
        if (active) {
            #pragma unroll
            for (int p = 0; p < 5; p++) {
                int co = cb + 2 * p;
                float2 bv = *(const float2*)&b3[co];
                float4 v0 = { acc[p][0].x + bv.x, acc[p][1].x + bv.x,
                              acc[p][2].x + bv.x, acc[p][3].x + bv.x };
                float4 v1 = { acc[p][0].y + bv.y, acc[p][1].y + bv.y,
                              acc[p][2].y + bv.y, acc[p][3].y + bv.y };
                *(float4*)&y[((size_t)(b * 80) + co    ) * 800 + t0 + tt] = v0;
                *(float4*)&y[((size_t)(b * 80) + co + 1) * 800 + t0 + tt] = v1;
            }
        }
    }
}

__global__ void stageB_kernel(
    const float* __restrict__ k1in, const float* __restrict__ kb2, float* __restrict__ kout,
    const float* __restrict__ q1in, const float* __restrict__ qb2,
    const float* __restrict__ qb3, float* __restrict__ qout)
{
    extern __shared__ float smem[];
    int id = blockIdx.x;
    if (id < 64) key1x1_body(k1in, g_kw2T, kb2, kout, id >> 2, id & 3, smem);
    else {
        int j = id - 64;
        qchain_body(q1in, g_qw2T, qb2, g_qw3T, qb3, qout, j / 7, j % 7, smem);
    }
}

// =================== STAGE C: L2-dist + log_softmax + log(prior) ==========
__global__ void attention_kernel(const float* __restrict__ q, const float* __restrict__ k,
                                 const float* __restrict__ prior, float* __restrict__ out)
{
    extern __shared__ float smem[];
    float* sq = smem;              // 80*16
    float* sd = smem + 1280;       // 16*200

    const int b    = blockIdx.y;
    const int t1_0 = blockIdx.x * 16;
    const int tid  = threadIdx.x;

    {
        int i = tid;
        if (i < 320) {
            int c = i >> 2, jq = (i & 3) << 2;
            *(float4*)&sq[c * 16 + jq] =
                *(const float4*)&q[((size_t)(b * 80) + c) * 800 + t1_0 + jq];
        }
        i = tid + 256;
        if (i < 320) {
            int c = i >> 2, jq = (i & 3) << 2;
            *(float4*)&sq[c * 16 + jq] =
                *(const float4*)&q[((size_t)(b * 80) + c) * 800 + t1_0 + jq];
        }
    }
    __syncthreads();

    const int sg = tid & 63, jg = tid >> 6;
    if (sg < 50) {
        const int s0 = sg * 4, j0 = jg * 4;
        const float* kp = &k[(size_t)(b * 80) * 200 + s0];
        float2 acc[4][2] = {};
        float2 k2p[2] = {}, q2p[2] = {};

        float4 kbuf[4];
        #pragma unroll
        for (int i = 0; i < 4; i++) kbuf[i] = *(const float4*)(kp + i * 200);

        #pragma unroll
        for (int c0 = 0; c0 < 80; c0 += 4) {
            float4 cur[4];
            #pragma unroll
            for (int i = 0; i < 4; i++) cur[i] = kbuf[i];
            if (c0 + 4 < 80) {
                #pragma unroll
                for (int i = 0; i < 4; i++)
                    kbuf[i] = *(const float4*)(kp + (c0 + 4 + i) * 200);
            }
            #pragma unroll
            for (int i = 0; i < 4; i++) {
                int c = c0 + i;
                float4 kq = cur[i];
                float4 qa = *(const float4*)&sq[c * 16 + j0];
                float2 qp[2] = { {qa.x, qa.y}, {qa.z, qa.w} };
                float2 kpair0 = { kq.x, kq.y }, kpair1 = { kq.z, kq.w };
                k2p[0] = ffma2(kpair0, kpair0, k2p[0]);
                k2p[1] = ffma2(kpair1, kpair1, k2p[1]);
                q2p[0] = ffma2(qp[0], qp[0], q2p[0]);
                q2p[1] = ffma2(qp[1], qp[1], q2p[1]);
                float ks[4] = { kq.x, kq.y, kq.z, kq.w };
                #pragma unroll
                for (int si = 0; si < 4; si++) {
                    float2 kd = dup(ks[si]);
                    acc[si][0] = ffma2(kd, qp[0], acc[si][0]);
                    acc[si][1] = ffma2(kd, qp[1], acc[si][1]);
                }
            }
        }
        float k2s[4] = { k2p[0].x, k2p[0].y, k2p[1].x, k2p[1].y };
        float q2s[4] = { q2p[0].x, q2p[0].y, q2p[1].x, q2p[1].y };
        #pragma unroll
        for (int jj = 0; jj < 4; jj++) {
            int p = jj >> 1;
            float a0 = (jj & 1) ? acc[0][p].y : acc[0][p].x;
            float a1 = (jj & 1) ? acc[1][p].y : acc[1][p].x;
            float a2 = (jj & 1) ? acc[2][p].y : acc[2][p].x;
            float a3 = (jj & 1) ? acc[3][p].y : acc[3][p].x;
            float4 v = { -0.0005f * (q2s[jj] + k2s[0] - 2.f * a0),
                         -0.0005f * (q2s[jj] + k2s[1] - 2.f * a1),
                         -0.0005f * (q2s[jj] + k2s[2] - 2.f * a2),
                         -0.0005f * (q2s[jj] + k2s[3] - 2.f * a3) };
            *(float4*)&sd[(j0 + jj) * 200 + s0] = v;
        }
    }
    __syncthreads();

    const int warp = tid >> 5, lane = tid & 31;
    #pragma unroll
    for (int rr = 0; rr < 2; rr++) {
        int j = warp + rr * 8;
        const float* pr = &prior[((size_t)b * 800 + t1_0 + j) * 200];
        float prv[7];
        #pragma unroll
        for (int i = 0; i < 7; i++) {
            int s = lane + 32 * i;
            prv[i] = (s < 200) ? pr[s] : 1.f;
        }
        float m = -1e30f;
        #pragma unroll
        for (int i = 0; i < 7; i++) {
            int s = lane + 32 * i;
            if (s < 200) m = fmaxf(m, sd[j * 200 + s]);
        }
        #pragma unroll
        for (int o = 16; o; o >>= 1) m = fmaxf(m, __shfl_xor_sync(0xffffffffu, m, o));
        float sum = 0.f;
        #pragma unroll
        for (int i = 0; i < 7; i++) {
            int s = lane + 32 * i;
            if (s < 200) sum += __expf(sd[j * 200 + s] - m);
        }
        #pragma unroll
        for (int o = 16; o; o >>= 1) sum += __shfl_xor_sync(0xffffffffu, sum, o);
        float lse = m + __logf(sum);
        float* op = &out[((size_t)b * 800 + t1_0 + j) * 200];
        #pragma unroll
        for (int i = 0; i < 7; i++) {
            int s = lane + 32 * i;
            if (s < 200) op[s] = sd[j * 200 + s] - lse + __logf(prv[i] + 1e-8f);
        }
    }
}

// -------------------------------- launch ---------------------------------
extern "C" void kernel_launch(void* const* d_in, const int* in_sizes, int n_in,
                              void* d_out, int out_size)
{
    const float* queries = (const float*)d_in[0];
    const float* keys    = (const float*)d_in[1];
    const float* prior   = (const float*)d_in[2];
    const float* kw1 = (const float*)d_in[3];
    const float* kb1 = (const float*)d_in[4];
    const float* kw2 = (const float*)d_in[5];
    const float* kb2 = (const float*)d_in[6];
    const float* qw1 = (const float*)d_in[7];
    const float* qb1 = (const float*)d_in[8];
    const float* qw2 = (const float*)d_in[9];
    const float* qb2 = (const float*)d_in[10];
    const float* qw3 = (const float*)d_in[11];
    const float* qb3 = (const float*)d_in[12];
    float* out = (float*)d_out;

    float *k1buf, *kbuf, *q1buf, *qbuf;
    float *kw1T, *qw1T, *kw2T, *qw2T, *qw3T;
    cudaGetSymbolAddress((void**)&k1buf, g_k1);
    cudaGetSymbolAddress((void**)&kbuf,  g_k);
    cudaGetSymbolAddress((void**)&q1buf, g_q1);
    cudaGetSymbolAddress((void**)&qbuf,  g_qf);
    cudaGetSymbolAddress((void**)&kw1T, g_kw1T);
    cudaGetSymbolAddress((void**)&qw1T, g_qw1T);
    cudaGetSymbolAddress((void**)&kw2T, g_kw2T);
    cudaGetSymbolAddress((void**)&qw2T, g_qw2T);
    cudaGetSymbolAddress((void**)&qw3T, g_qw3T);

    const int smem_A    = (16 * 68 + 48 * 160) * 4;              // 35072
    const int smem_B    = (4096 + 2560 + 80 * 128) * 4;          // 67584
    const int smem_attn = (1280 + 16 * 200) * 4;                 // 17920

    cudaFuncSetAttribute((const void*)stageA_kernel,
                         cudaFuncAttributeMaxDynamicSharedMemorySize, smem_A);
    cudaFuncSetAttribute((const void*)stageB_kernel,
                         cudaFuncAttributeMaxDynamicSharedMemorySize, smem_B);

    prep_kernel<<<1921, 256>>>(kw1, qw1, kw2, qw2, qw3, kw1T, qw1T, kw2T, qw2T, qw3T);
    stageA_kernel<<<720, 256, smem_A>>>(keys, kb1, queries, qb1, k1buf, q1buf);
    stageB_kernel<<<176, 256, smem_B>>>(k1buf, kb2, kbuf, q1buf, qb2, qb3, qbuf);
    attention_kernel<<<dim3(50, 16), 256, smem_attn>>>(qbuf, kbuf, prior, out);
}